// round 1
// baseline (speedup 1.0000x reference)
#include <cuda_runtime.h>
#include <math.h>

#define T_TOK 2048
#define DIM   1024
#define INTER 512
#define NEXP  16
#define TOPK  4
#define NGRP  4
#define GSZ   4     // experts per group
#define NE1   (NEXP + 1)   // +1 = shared expert

// ---------------- scratch (device globals; no allocations) ----------------
__device__ int           g_cnt[NEXP];
__device__ int           g_tok[NEXP][T_TOK];
__device__ unsigned char g_slot[NEXP][T_TOK];
__device__ float         g_wt[NEXP][T_TOK];
__device__ float         g_h[(size_t)NE1 * T_TOK * INTER];     // 71.3 MB
__device__ float         g_ybuf[TOPK][(size_t)T_TOK * DIM];    // 32 MB

// ---------------- init ----------------
__global__ void init_kernel() {
    int i = threadIdx.x;
    if (i < NEXP) g_cnt[i] = 0;
}

// ---------------- gate: 1 warp per token ----------------
__global__ void gate_kernel(const float* __restrict__ x,
                            const float* __restrict__ gw,
                            const float* __restrict__ gbias) {
    int t    = blockIdx.x;
    int lane = threadIdx.x;

    // keep x row in registers: 32 floats per lane
    float xr[32];
    const float* xp = x + (size_t)t * DIM;
#pragma unroll
    for (int i = 0; i < 32; i++) xr[i] = xp[lane + i * 32];

    float sc[NEXP];
#pragma unroll
    for (int e = 0; e < NEXP; e++) {
        const float* w = gw + (size_t)e * DIM;
        float acc = 0.f;
#pragma unroll
        for (int i = 0; i < 32; i++) acc += xr[i] * w[lane + i * 32];
#pragma unroll
        for (int o = 16; o > 0; o >>= 1) acc += __shfl_xor_sync(0xffffffffu, acc, o);
        sc[e] = 1.f / (1.f + expf(-acc));   // sigmoid score
    }

    if (lane == 0) {
        float s[NEXP];
#pragma unroll
        for (int e = 0; e < NEXP; e++) s[e] = sc[e] + gbias[e];

        // group maxes
        float gm[NGRP];
#pragma unroll
        for (int g = 0; g < NGRP; g++) {
            float m = s[g * GSZ];
#pragma unroll
            for (int j = 1; j < GSZ; j++) m = fmaxf(m, s[g * GSZ + j]);
            gm[g] = m;
        }
        // top-2 groups (strict > keeps earliest index on ties, like jax.top_k)
        int g1 = 0;
#pragma unroll
        for (int g = 1; g < NGRP; g++) if (gm[g] > gm[g1]) g1 = g;
        int g2 = -1;
#pragma unroll
        for (int g = 0; g < NGRP; g++) {
            if (g == g1) continue;
            if (g2 < 0 || gm[g] > gm[g2]) g2 = g;
        }

        float sm[NEXP];
#pragma unroll
        for (int e = 0; e < NEXP; e++) {
            int g = e / GSZ;
            sm[e] = (g == g1 || g == g2) ? s[e] : -1e30f;
        }
        // top-4 experts
#pragma unroll
        for (int k = 0; k < TOPK; k++) {
            int best = 0; float bv = -1e38f;
#pragma unroll
            for (int e = 0; e < NEXP; e++) if (sm[e] > bv) { bv = sm[e]; best = e; }
            sm[best] = -1e38f;
            int pos = atomicAdd(&g_cnt[best], 1);
            g_tok[best][pos]  = t;
            g_slot[best][pos] = (unsigned char)k;
            g_wt[best][pos]   = sc[best];   // ROUTE_SCALE = 1
        }
    }
}

// ---------------- stage A: h = silu(X @ W1^T) * (X @ W3^T), grouped ----------------
// grid: (m_tiles=32, n_tiles=INTER/64=8, e=17). Block 256 threads, 64x64 tile, BK=16.
__global__ __launch_bounds__(256) void ffn_in_kernel(
    const float* __restrict__ x,
    const float* __restrict__ w1, const float* __restrict__ w3,
    const float* __restrict__ ws1, const float* __restrict__ ws3)
{
    const int e   = blockIdx.z;
    const int cnt = (e == NEXP) ? T_TOK : g_cnt[e];
    const int m0  = blockIdx.x * 64;
    if (m0 >= cnt) return;
    const int n0  = blockIdx.y * 64;

    const float* W1 = (e == NEXP) ? ws1 : w1 + (size_t)e * INTER * DIM;
    const float* W3 = (e == NEXP) ? ws3 : w3 + (size_t)e * INTER * DIM;

    __shared__ float As[16][64];
    __shared__ float B1s[16][64];
    __shared__ float B3s[16][64];

    const int tid  = threadIdx.x;
    const int arow = tid >> 2, acg = tid & 3;   // 64 rows x 4 float4-cols

    // gather token index for the A row this thread loads
    int tokA;
    if (e == NEXP) tokA = m0 + arow;
    else {
        int idx = m0 + arow; if (idx > T_TOK - 1) idx = T_TOK - 1;
        tokA = g_tok[e][idx];
        if (tokA < 0) tokA = 0; if (tokA > T_TOK - 1) tokA = T_TOK - 1;
    }
    const float* aPtr  = x + (size_t)tokA * DIM;
    const float* b1Ptr = W1 + (size_t)(n0 + arow) * DIM;
    const float* b3Ptr = W3 + (size_t)(n0 + arow) * DIM;

    const int tx = tid & 15, ty = tid >> 4;
    float acc1[4][4] = {}, acc3[4][4] = {};

    for (int kk = 0; kk < DIM / 16; kk++) {
        const int kb = kk * 16 + acg * 4;
        float4 a4 = *(const float4*)(aPtr + kb);
        float4 b1 = *(const float4*)(b1Ptr + kb);
        float4 b3 = *(const float4*)(b3Ptr + kb);
        __syncthreads();
        As[acg * 4 + 0][arow] = a4.x; As[acg * 4 + 1][arow] = a4.y;
        As[acg * 4 + 2][arow] = a4.z; As[acg * 4 + 3][arow] = a4.w;
        B1s[acg * 4 + 0][arow] = b1.x; B1s[acg * 4 + 1][arow] = b1.y;
        B1s[acg * 4 + 2][arow] = b1.z; B1s[acg * 4 + 3][arow] = b1.w;
        B3s[acg * 4 + 0][arow] = b3.x; B3s[acg * 4 + 1][arow] = b3.y;
        B3s[acg * 4 + 2][arow] = b3.z; B3s[acg * 4 + 3][arow] = b3.w;
        __syncthreads();

#pragma unroll
        for (int k = 0; k < 16; k++) {
            float4 a  = *(const float4*)&As[k][ty * 4];
            float4 f1 = *(const float4*)&B1s[k][tx * 4];
            float4 f3 = *(const float4*)&B3s[k][tx * 4];
            float av[4] = {a.x, a.y, a.z, a.w};
            float v1[4] = {f1.x, f1.y, f1.z, f1.w};
            float v3[4] = {f3.x, f3.y, f3.z, f3.w};
#pragma unroll
            for (int i = 0; i < 4; i++)
#pragma unroll
                for (int j = 0; j < 4; j++) {
                    acc1[i][j] += av[i] * v1[j];
                    acc3[i][j] += av[i] * v3[j];
                }
        }
    }

    // epilogue: silu(h1)*h3 -> g_h
#pragma unroll
    for (int i = 0; i < 4; i++) {
        int m = m0 + ty * 4 + i;
        if (m >= cnt) continue;
        float4 o;
        float* po = &o.x;
#pragma unroll
        for (int j = 0; j < 4; j++) {
            float v1 = acc1[i][j], v3 = acc3[i][j];
            po[j] = (v1 / (1.f + expf(-v1))) * v3;
        }
        *(float4*)(&g_h[((size_t)e * T_TOK + m) * INTER + n0 + tx * 4]) = o;
    }
}

// ---------------- stage B: yc = (H @ W2^T) * weight, grouped ----------------
// grid: (m_tiles=32, n_tiles=DIM/64=16, e=17). Same tiling, K=INTER=512.
__global__ __launch_bounds__(256) void ffn_out_kernel(
    const float* __restrict__ w2, const float* __restrict__ ws2,
    float* __restrict__ out)
{
    const int e   = blockIdx.z;
    const int cnt = (e == NEXP) ? T_TOK : g_cnt[e];
    const int m0  = blockIdx.x * 64;
    if (m0 >= cnt) return;
    const int n0  = blockIdx.y * 64;

    const float* W2 = (e == NEXP) ? ws2 : w2 + (size_t)e * DIM * INTER;

    __shared__ float As[16][64];
    __shared__ float Bs[16][64];

    const int tid  = threadIdx.x;
    const int arow = tid >> 2, acg = tid & 3;

    int hrow = m0 + arow; if (hrow > T_TOK - 1) hrow = T_TOK - 1;
    const float* aPtr = &g_h[((size_t)e * T_TOK + hrow) * INTER];
    const float* bPtr = W2 + (size_t)(n0 + arow) * INTER;

    const int tx = tid & 15, ty = tid >> 4;
    float acc[4][4] = {};

    for (int kk = 0; kk < INTER / 16; kk++) {
        const int kb = kk * 16 + acg * 4;
        float4 a4 = *(const float4*)(aPtr + kb);
        float4 b4 = *(const float4*)(bPtr + kb);
        __syncthreads();
        As[acg * 4 + 0][arow] = a4.x; As[acg * 4 + 1][arow] = a4.y;
        As[acg * 4 + 2][arow] = a4.z; As[acg * 4 + 3][arow] = a4.w;
        Bs[acg * 4 + 0][arow] = b4.x; Bs[acg * 4 + 1][arow] = b4.y;
        Bs[acg * 4 + 2][arow] = b4.z; Bs[acg * 4 + 3][arow] = b4.w;
        __syncthreads();

#pragma unroll
        for (int k = 0; k < 16; k++) {
            float4 a = *(const float4*)&As[k][ty * 4];
            float4 b = *(const float4*)&Bs[k][tx * 4];
            float av[4] = {a.x, a.y, a.z, a.w};
            float bv[4] = {b.x, b.y, b.z, b.w};
#pragma unroll
            for (int i = 0; i < 4; i++)
#pragma unroll
                for (int j = 0; j < 4; j++)
                    acc[i][j] += av[i] * bv[j];
        }
    }

#pragma unroll
    for (int i = 0; i < 4; i++) {
        int m = m0 + ty * 4 + i;
        if (m >= cnt) continue;
        if (e == NEXP) {
            // shared expert -> write out directly (weight 1)
            float4 o = make_float4(acc[i][0], acc[i][1], acc[i][2], acc[i][3]);
            *(float4*)(out + (size_t)m * DIM + n0 + tx * 4) = o;
        } else {
            int   tok = g_tok[e][m];
            int   sl  = g_slot[e][m];
            float w   = g_wt[e][m];
            float4 o = make_float4(acc[i][0] * w, acc[i][1] * w,
                                   acc[i][2] * w, acc[i][3] * w);
            *(float4*)(&g_ybuf[sl][(size_t)tok * DIM + n0 + tx * 4]) = o;
        }
    }
}

// ---------------- reduce: out += sum_k ybuf[k] ----------------
__global__ void reduce_kernel(float* __restrict__ out) {
    size_t idx = (size_t)blockIdx.x * blockDim.x + threadIdx.x;
    if (idx < (size_t)T_TOK * DIM) {
        out[idx] += g_ybuf[0][idx] + g_ybuf[1][idx] + g_ybuf[2][idx] + g_ybuf[3][idx];
    }
}

// ---------------- launch ----------------
extern "C" void kernel_launch(void* const* d_in, const int* in_sizes, int n_in,
                              void* d_out, int out_size) {
    const float* x   = (const float*)d_in[0];
    const float* gw  = (const float*)d_in[1];
    const float* gb  = (const float*)d_in[2];
    const float* w1  = (const float*)d_in[3];
    const float* w2  = (const float*)d_in[4];
    const float* w3  = (const float*)d_in[5];
    const float* ws1 = (const float*)d_in[6];
    const float* ws2 = (const float*)d_in[7];
    const float* ws3 = (const float*)d_in[8];
    float* out = (float*)d_out;

    init_kernel<<<1, 32>>>();
    gate_kernel<<<T_TOK, 32>>>(x, gw, gb);
    ffn_in_kernel<<<dim3(T_TOK / 64, INTER / 64, NE1), 256>>>(x, w1, w3, ws1, ws3);
    ffn_out_kernel<<<dim3(T_TOK / 64, DIM / 64, NE1), 256>>>(w2, ws2, out);
    reduce_kernel<<<(T_TOK * DIM + 255) / 256, 256>>>(out);
}

// round 3
// speedup vs baseline: 1.3260x; 1.3260x over previous
#include <cuda_runtime.h>
#include <math.h>
#include <stdint.h>

#define T_TOK 2048
#define DIM   1024
#define INTER 512
#define NEXP  16
#define TOPK  4
#define NGRP  4
#define GSZ   4
#define NE1   (NEXP + 1)   // +1 = shared expert

// ---------------- scratch (device globals; no allocations) ----------------
__device__ int           g_cnt[NEXP];
__device__ int           g_tok[NEXP][T_TOK];
__device__ unsigned char g_slot[NEXP][T_TOK];
__device__ float         g_wt[NEXP][T_TOK];
__device__ float         g_h1[(size_t)NE1 * T_TOK * INTER];    // 71.3 MB
__device__ float         g_h3[(size_t)NE1 * T_TOK * INTER];    // 71.3 MB
__device__ float         g_ybuf[TOPK][(size_t)T_TOK * DIM];    // 32 MB

// ---------------- helpers ----------------
__device__ __forceinline__ uint32_t f2tf32(float f) {
    uint32_t u;
    asm("cvt.rna.tf32.f32 %0, %1;" : "=r"(u) : "f"(f));
    return u;
}

__device__ __forceinline__ void mma_tf32(float* d, const uint32_t* a, const uint32_t* b) {
    asm volatile(
        "mma.sync.aligned.m16n8k8.row.col.f32.tf32.tf32.f32 "
        "{%0,%1,%2,%3}, {%4,%5,%6,%7}, {%8,%9}, {%0,%1,%2,%3};"
        : "+f"(d[0]), "+f"(d[1]), "+f"(d[2]), "+f"(d[3])
        : "r"(a[0]), "r"(a[1]), "r"(a[2]), "r"(a[3]), "r"(b[0]), "r"(b[1]));
}

// ---------------- init ----------------
__global__ void init_kernel() {
    int i = threadIdx.x;
    if (i < NEXP) g_cnt[i] = 0;
}

// ---------------- gate: 1 warp per token (fp32, exact selection) ----------------
__global__ void gate_kernel(const float* __restrict__ x,
                            const float* __restrict__ gw,
                            const float* __restrict__ gbias) {
    int t    = blockIdx.x;
    int lane = threadIdx.x;

    float xr[32];
    const float* xp = x + (size_t)t * DIM;
#pragma unroll
    for (int i = 0; i < 32; i++) xr[i] = xp[lane + i * 32];

    float sc[NEXP];
#pragma unroll
    for (int e = 0; e < NEXP; e++) {
        const float* w = gw + (size_t)e * DIM;
        float acc = 0.f;
#pragma unroll
        for (int i = 0; i < 32; i++) acc += xr[i] * w[lane + i * 32];
#pragma unroll
        for (int o = 16; o > 0; o >>= 1) acc += __shfl_xor_sync(0xffffffffu, acc, o);
        sc[e] = 1.f / (1.f + expf(-acc));
    }

    if (lane == 0) {
        float s[NEXP];
#pragma unroll
        for (int e = 0; e < NEXP; e++) s[e] = sc[e] + gbias[e];

        float gm[NGRP];
#pragma unroll
        for (int g = 0; g < NGRP; g++) {
            float m = s[g * GSZ];
#pragma unroll
            for (int j = 1; j < GSZ; j++) m = fmaxf(m, s[g * GSZ + j]);
            gm[g] = m;
        }
        int g1 = 0;
#pragma unroll
        for (int g = 1; g < NGRP; g++) if (gm[g] > gm[g1]) g1 = g;
        int g2 = -1;
#pragma unroll
        for (int g = 0; g < NGRP; g++) {
            if (g == g1) continue;
            if (g2 < 0 || gm[g] > gm[g2]) g2 = g;
        }

        float sm[NEXP];
#pragma unroll
        for (int e = 0; e < NEXP; e++) {
            int g = e / GSZ;
            sm[e] = (g == g1 || g == g2) ? s[e] : -1e30f;
        }
#pragma unroll
        for (int k = 0; k < TOPK; k++) {
            int best = 0; float bv = -1e38f;
#pragma unroll
            for (int e = 0; e < NEXP; e++) if (sm[e] > bv) { bv = sm[e]; best = e; }
            sm[best] = -1e38f;
            int pos = atomicAdd(&g_cnt[best], 1);
            g_tok[best][pos]  = t;
            g_slot[best][pos] = (unsigned char)k;
            g_wt[best][pos]   = sc[best];
        }
    }
}

// =====================================================================
// stage A: h1 = X @ W1^T (ny<4) / h3 = X @ W3^T (ny>=4), tf32 mma.sync
// grid (16, 8, 17), block 256 (8 warps, 2x4). Tile M=128 N=128 BK=32.
// =====================================================================
#define SSTRIDE 36

__global__ __launch_bounds__(256) void ffn_in_mma(
    const float* __restrict__ x,
    const float* __restrict__ w1, const float* __restrict__ w3,
    const float* __restrict__ ws1, const float* __restrict__ ws3)
{
    const int e   = blockIdx.z;
    const int cnt = (e == NEXP) ? T_TOK : g_cnt[e];
    const int m0  = blockIdx.x * 128;
    if (m0 >= cnt) return;
    const int  ny  = blockIdx.y;
    const bool is3 = (ny >= 4);
    const int  n0  = (ny & 3) * 128;

    const float* W = is3 ? ((e == NEXP) ? ws3 : w3 + (size_t)e * INTER * DIM)
                         : ((e == NEXP) ? ws1 : w1 + (size_t)e * INTER * DIM);

    __shared__ __align__(16) float As[128 * SSTRIDE];
    __shared__ __align__(16) float Bs[128 * SSTRIDE];

    const int tid = threadIdx.x;
    const int r   = tid >> 1, hf = tid & 1;

    int aidx = m0 + r; if (aidx > cnt - 1) aidx = cnt - 1;
    const int tok = (e == NEXP) ? (m0 + r) : g_tok[e][aidx];
    const float* aRow = x + (size_t)tok * DIM + hf * 16;
    const float* bRow = W + (size_t)(n0 + r) * DIM + hf * 16;

    const int lane = tid & 31, warp = tid >> 5;
    const int wm = warp >> 2, wn = warp & 3;    // 2 x 4 warps
    const int gid = lane >> 2, tig = lane & 3;

    float acc[4][4][4];
#pragma unroll
    for (int i = 0; i < 4; i++)
#pragma unroll
        for (int j = 0; j < 4; j++)
#pragma unroll
            for (int k = 0; k < 4; k++) acc[i][j][k] = 0.f;

    float4 aL[4], bL[4];
#pragma unroll
    for (int q = 0; q < 4; q++) {
        aL[q] = *(const float4*)(aRow + q * 4);
        bL[q] = *(const float4*)(bRow + q * 4);
    }

    const int sbase = r * SSTRIDE + hf * 16;
    for (int kk = 0; kk < DIM / 32; kk++) {
        __syncthreads();
#pragma unroll
        for (int q = 0; q < 4; q++) {
            uint4 ua, ub;
            ua.x = f2tf32(aL[q].x); ua.y = f2tf32(aL[q].y);
            ua.z = f2tf32(aL[q].z); ua.w = f2tf32(aL[q].w);
            ub.x = f2tf32(bL[q].x); ub.y = f2tf32(bL[q].y);
            ub.z = f2tf32(bL[q].z); ub.w = f2tf32(bL[q].w);
            *(uint4*)(As + sbase + q * 4) = ua;
            *(uint4*)(Bs + sbase + q * 4) = ub;
        }
        __syncthreads();
        if (kk + 1 < DIM / 32) {
            const float* ga = aRow + (kk + 1) * 32;
            const float* gb = bRow + (kk + 1) * 32;
#pragma unroll
            for (int q = 0; q < 4; q++) {
                aL[q] = *(const float4*)(ga + q * 4);
                bL[q] = *(const float4*)(gb + q * 4);
            }
        }
#pragma unroll
        for (int ks = 0; ks < 4; ks++) {
            const int k0 = ks * 8;
            uint32_t af[4][4], bf[4][2];
#pragma unroll
            for (int mt = 0; mt < 4; mt++) {
                const float* ap = As + (wm * 64 + mt * 16 + gid) * SSTRIDE + k0 + tig;
                af[mt][0] = __float_as_uint(ap[0]);
                af[mt][1] = __float_as_uint(ap[8 * SSTRIDE]);
                af[mt][2] = __float_as_uint(ap[4]);
                af[mt][3] = __float_as_uint(ap[8 * SSTRIDE + 4]);
            }
#pragma unroll
            for (int nt = 0; nt < 4; nt++) {
                const float* bp = Bs + (wn * 32 + nt * 8 + gid) * SSTRIDE + k0 + tig;
                bf[nt][0] = __float_as_uint(bp[0]);
                bf[nt][1] = __float_as_uint(bp[4]);
            }
#pragma unroll
            for (int mt = 0; mt < 4; mt++)
#pragma unroll
                for (int nt = 0; nt < 4; nt++)
                    mma_tf32(acc[mt][nt], af[mt], bf[nt]);
        }
    }

    float* H = is3 ? g_h3 : g_h1;
#pragma unroll
    for (int mt = 0; mt < 4; mt++) {
        const int mrow = m0 + wm * 64 + mt * 16 + gid;
#pragma unroll
        for (int nt = 0; nt < 4; nt++) {
            const int col = n0 + wn * 32 + nt * 8 + tig * 2;
            if (mrow < cnt)
                *(float2*)&H[((size_t)e * T_TOK + mrow) * INTER + col] =
                    make_float2(acc[mt][nt][0], acc[mt][nt][1]);
            if (mrow + 8 < cnt)
                *(float2*)&H[((size_t)e * T_TOK + mrow + 8) * INTER + col] =
                    make_float2(acc[mt][nt][2], acc[mt][nt][3]);
        }
    }
}

// =====================================================================
// stage B: y = (silu(h1)*h3) @ W2^T  (* route weight), tf32 mma.sync
// grid (16, 8, 17), block 256. Tile M=128 N=128 BK=32, K=INTER=512.
// =====================================================================
__global__ __launch_bounds__(256) void ffn_out_mma(
    const float* __restrict__ w2, const float* __restrict__ ws2,
    float* __restrict__ out)
{
    const int e   = blockIdx.z;
    const int cnt = (e == NEXP) ? T_TOK : g_cnt[e];
    const int m0  = blockIdx.x * 128;
    if (m0 >= cnt) return;
    const int n0  = blockIdx.y * 128;

    const float* W2 = (e == NEXP) ? ws2 : w2 + (size_t)e * DIM * INTER;

    __shared__ __align__(16) float As[128 * SSTRIDE];
    __shared__ __align__(16) float Bs[128 * SSTRIDE];

    const int tid = threadIdx.x;
    const int r   = tid >> 1, hf = tid & 1;

    int aidx = m0 + r; if (aidx > cnt - 1) aidx = cnt - 1;
    const float* h1Row = g_h1 + ((size_t)e * T_TOK + aidx) * INTER + hf * 16;
    const float* h3Row = g_h3 + ((size_t)e * T_TOK + aidx) * INTER + hf * 16;
    const float* bRow  = W2 + (size_t)(n0 + r) * INTER + hf * 16;

    const int lane = tid & 31, warp = tid >> 5;
    const int wm = warp >> 2, wn = warp & 3;
    const int gid = lane >> 2, tig = lane & 3;

    float acc[4][4][4];
#pragma unroll
    for (int i = 0; i < 4; i++)
#pragma unroll
        for (int j = 0; j < 4; j++)
#pragma unroll
            for (int k = 0; k < 4; k++) acc[i][j][k] = 0.f;

    float4 a1L[4], a3L[4], bL[4];
#pragma unroll
    for (int q = 0; q < 4; q++) {
        a1L[q] = *(const float4*)(h1Row + q * 4);
        a3L[q] = *(const float4*)(h3Row + q * 4);
        bL[q]  = *(const float4*)(bRow + q * 4);
    }

    const int sbase = r * SSTRIDE + hf * 16;
    for (int kk = 0; kk < INTER / 32; kk++) {
        __syncthreads();
#pragma unroll
        for (int q = 0; q < 4; q++) {
            uint4 ua, ub;
            // act = silu(h1) * h3, rounded to tf32
            float v;
            v = a1L[q].x; ua.x = f2tf32((v / (1.f + __expf(-v))) * a3L[q].x);
            v = a1L[q].y; ua.y = f2tf32((v / (1.f + __expf(-v))) * a3L[q].y);
            v = a1L[q].z; ua.z = f2tf32((v / (1.f + __expf(-v))) * a3L[q].z);
            v = a1L[q].w; ua.w = f2tf32((v / (1.f + __expf(-v))) * a3L[q].w);
            ub.x = f2tf32(bL[q].x); ub.y = f2tf32(bL[q].y);
            ub.z = f2tf32(bL[q].z); ub.w = f2tf32(bL[q].w);
            *(uint4*)(As + sbase + q * 4) = ua;
            *(uint4*)(Bs + sbase + q * 4) = ub;
        }
        __syncthreads();
        if (kk + 1 < INTER / 32) {
            const float* g1 = h1Row + (kk + 1) * 32;
            const float* g3 = h3Row + (kk + 1) * 32;
            const float* gb = bRow  + (kk + 1) * 32;
#pragma unroll
            for (int q = 0; q < 4; q++) {
                a1L[q] = *(const float4*)(g1 + q * 4);
                a3L[q] = *(const float4*)(g3 + q * 4);
                bL[q]  = *(const float4*)(gb + q * 4);
            }
        }
#pragma unroll
        for (int ks = 0; ks < 4; ks++) {
            const int k0 = ks * 8;
            uint32_t af[4][4], bf[4][2];
#pragma unroll
            for (int mt = 0; mt < 4; mt++) {
                const float* ap = As + (wm * 64 + mt * 16 + gid) * SSTRIDE + k0 + tig;
                af[mt][0] = __float_as_uint(ap[0]);
                af[mt][1] = __float_as_uint(ap[8 * SSTRIDE]);
                af[mt][2] = __float_as_uint(ap[4]);
                af[mt][3] = __float_as_uint(ap[8 * SSTRIDE + 4]);
            }
#pragma unroll
            for (int nt = 0; nt < 4; nt++) {
                const float* bp = Bs + (wn * 32 + nt * 8 + gid) * SSTRIDE + k0 + tig;
                bf[nt][0] = __float_as_uint(bp[0]);
                bf[nt][1] = __float_as_uint(bp[4]);
            }
#pragma unroll
            for (int mt = 0; mt < 4; mt++)
#pragma unroll
                for (int nt = 0; nt < 4; nt++)
                    mma_tf32(acc[mt][nt], af[mt], bf[nt]);
        }
    }

    // epilogue: route to ybuf (routed, * weight) or out (shared expert)
#pragma unroll
    for (int mt = 0; mt < 4; mt++) {
        const int mrow = m0 + wm * 64 + mt * 16 + gid;
#pragma unroll
        for (int half8 = 0; half8 < 2; half8++) {
            const int m = mrow + half8 * 8;
            if (m >= cnt) continue;
            float wt = 1.f;
            float* dst;
            if (e == NEXP) {
                dst = out + (size_t)m * DIM + n0;
            } else {
                const int   tokm = g_tok[e][m];
                const int   sl   = g_slot[e][m];
                wt               = g_wt[e][m];
                dst = &g_ybuf[sl][(size_t)tokm * DIM + n0];
            }
#pragma unroll
            for (int nt = 0; nt < 4; nt++) {
                const int col = wn * 32 + nt * 8 + tig * 2;
                *(float2*)(dst + col) =
                    make_float2(acc[mt][nt][half8 * 2 + 0] * wt,
                                acc[mt][nt][half8 * 2 + 1] * wt);
            }
        }
    }
}

// ---------------- reduce: out += sum_k ybuf[k] ----------------
__global__ void reduce_kernel(float* __restrict__ out) {
    size_t idx = (size_t)blockIdx.x * blockDim.x + threadIdx.x;
    if (idx < (size_t)T_TOK * DIM) {
        out[idx] += g_ybuf[0][idx] + g_ybuf[1][idx] + g_ybuf[2][idx] + g_ybuf[3][idx];
    }
}

// ---------------- launch ----------------
extern "C" void kernel_launch(void* const* d_in, const int* in_sizes, int n_in,
                              void* d_out, int out_size) {
    const float* x   = (const float*)d_in[0];
    const float* gw  = (const float*)d_in[1];
    const float* gb  = (const float*)d_in[2];
    const float* w1  = (const float*)d_in[3];
    const float* w2  = (const float*)d_in[4];
    const float* w3  = (const float*)d_in[5];
    const float* ws1 = (const float*)d_in[6];
    const float* ws2 = (const float*)d_in[7];
    const float* ws3 = (const float*)d_in[8];
    float* out = (float*)d_out;

    init_kernel<<<1, 32>>>();
    gate_kernel<<<T_TOK, 32>>>(x, gw, gb);
    ffn_in_mma<<<dim3(T_TOK / 128, 8, NE1), 256>>>(x, w1, w3, ws1, ws3);
    ffn_out_mma<<<dim3(T_TOK / 128, DIM / 128, NE1), 256>>>(w2, ws2, out);
    reduce_kernel<<<(T_TOK * DIM + 255) / 256, 256>>>(out);
}

// round 4
// speedup vs baseline: 2.3229x; 1.7518x over previous
#include <cuda_runtime.h>
#include <math.h>
#include <stdint.h>

#define T_TOK 2048
#define DIM   1024
#define INTER 512
#define NEXP  16
#define TOPK  4
#define NGRP  4
#define GSZ   4
#define NE1   (NEXP + 1)   // +1 = shared expert

#define SS 36                      // smem row stride (floats), 144B: 16B-aligned, conflict-free
#define STG_FLOATS (128*SS + 64*SS + 64*SS)   // stage A layout; stage B uses same total
#define SMEM_BYTES (3 * STG_FLOATS * 4)       // 110592

// ---------------- scratch ----------------
__device__ int           g_cnt[NEXP];
__device__ int           g_tok[NEXP][T_TOK];
__device__ unsigned char g_slot[NEXP][T_TOK];
__device__ float         g_wt[NEXP][T_TOK];
__device__ float         g_act[(size_t)NE1 * T_TOK * INTER];   // 71.3 MB
__device__ float         g_ybuf[TOPK][(size_t)T_TOK * DIM];    // 32 MB

// ---------------- helpers ----------------
__device__ __forceinline__ uint32_t smem_u32(const void* p) {
    uint32_t a;
    asm("{ .reg .u64 t; cvta.to.shared.u64 t, %1; cvt.u32.u64 %0, t; }" : "=r"(a) : "l"(p));
    return a;
}
__device__ __forceinline__ uint32_t f2tf32(float f) {
    uint32_t u;
    asm("cvt.rna.tf32.f32 %0, %1;" : "=r"(u) : "f"(f));
    return u;
}
__device__ __forceinline__ void cp16(uint32_t dst, const void* src) {
    asm volatile("cp.async.ca.shared.global [%0], [%1], 16;" :: "r"(dst), "l"(src));
}
#define CP_COMMIT() asm volatile("cp.async.commit_group;")
#define CP_WAIT1()  asm volatile("cp.async.wait_group 1;")

__device__ __forceinline__ void mma_tf32(float* d, const uint32_t* a, const uint32_t* b) {
    asm volatile(
        "mma.sync.aligned.m16n8k8.row.col.f32.tf32.tf32.f32 "
        "{%0,%1,%2,%3}, {%4,%5,%6,%7}, {%8,%9}, {%0,%1,%2,%3};"
        : "+f"(d[0]), "+f"(d[1]), "+f"(d[2]), "+f"(d[3])
        : "r"(a[0]), "r"(a[1]), "r"(a[2]), "r"(a[3]), "r"(b[0]), "r"(b[1]));
}

// ---------------- init ----------------
__global__ void init_kernel() {
    int i = threadIdx.x;
    if (i < NEXP) g_cnt[i] = 0;
}

// ---------------- gate: 1 warp per token ----------------
__global__ void gate_kernel(const float* __restrict__ x,
                            const float* __restrict__ gw,
                            const float* __restrict__ gbias) {
    int t = blockIdx.x, lane = threadIdx.x;
    float xr[32];
    const float* xp = x + (size_t)t * DIM;
#pragma unroll
    for (int i = 0; i < 32; i++) xr[i] = xp[lane + i * 32];

    float sc[NEXP];
#pragma unroll
    for (int e = 0; e < NEXP; e++) {
        const float* w = gw + (size_t)e * DIM;
        float acc = 0.f;
#pragma unroll
        for (int i = 0; i < 32; i++) acc += xr[i] * w[lane + i * 32];
#pragma unroll
        for (int o = 16; o > 0; o >>= 1) acc += __shfl_xor_sync(0xffffffffu, acc, o);
        sc[e] = 1.f / (1.f + expf(-acc));
    }
    if (lane == 0) {
        float s[NEXP];
#pragma unroll
        for (int e = 0; e < NEXP; e++) s[e] = sc[e] + gbias[e];
        float gm[NGRP];
#pragma unroll
        for (int g = 0; g < NGRP; g++) {
            float m = s[g * GSZ];
#pragma unroll
            for (int j = 1; j < GSZ; j++) m = fmaxf(m, s[g * GSZ + j]);
            gm[g] = m;
        }
        int g1 = 0;
#pragma unroll
        for (int g = 1; g < NGRP; g++) if (gm[g] > gm[g1]) g1 = g;
        int g2 = -1;
#pragma unroll
        for (int g = 0; g < NGRP; g++) {
            if (g == g1) continue;
            if (g2 < 0 || gm[g] > gm[g2]) g2 = g;
        }
        float sm[NEXP];
#pragma unroll
        for (int e = 0; e < NEXP; e++) {
            int g = e / GSZ;
            sm[e] = (g == g1 || g == g2) ? s[e] : -1e30f;
        }
#pragma unroll
        for (int k = 0; k < TOPK; k++) {
            int best = 0; float bv = -1e38f;
#pragma unroll
            for (int e = 0; e < NEXP; e++) if (sm[e] > bv) { bv = sm[e]; best = e; }
            sm[best] = -1e38f;
            int pos = atomicAdd(&g_cnt[best], 1);
            g_tok[best][pos]  = t;
            g_slot[best][pos] = (unsigned char)k;
            g_wt[best][pos]   = sc[best];
        }
    }
}

// =====================================================================
// stage A: act = silu(X@W1^T) * (X@W3^T)   (fused, cp.async pipelined)
// grid (16, INTER/64=8, 17), block 256 (8 warps as 4x2).
// Block tile: M=128, N=64 for BOTH W1 and W3; BK=32; 3-stage pipeline.
// =====================================================================
__global__ __launch_bounds__(256, 2) void ffn_in_mma(
    const float* __restrict__ x,
    const float* __restrict__ w1, const float* __restrict__ w3,
    const float* __restrict__ ws1, const float* __restrict__ ws3)
{
    const int e   = blockIdx.z;
    const int cnt = (e == NEXP) ? T_TOK : g_cnt[e];
    const int m0  = blockIdx.x * 128;
    if (m0 >= cnt) return;
    const int n0  = blockIdx.y * 64;

    const float* W1 = (e == NEXP) ? ws1 : w1 + (size_t)e * INTER * DIM;
    const float* W3 = (e == NEXP) ? ws3 : w3 + (size_t)e * INTER * DIM;

    extern __shared__ float smf[];
    const uint32_t sb = smem_u32(smf);
    const int tid = threadIdx.x;

    // --- copy assignments ---
    // A: row = tid>>1 (128 rows), 16 floats starting at (tid&1)*16
    const int arow = tid >> 1, aseg = (tid & 1) * 16;
    int aidx = m0 + arow; if (aidx > cnt - 1) aidx = cnt - 1;
    const int tok = (e == NEXP) ? (m0 + arow) : g_tok[e][aidx];
    const float* aSrc = x + (size_t)tok * DIM + aseg;
    const uint32_t aDstB = (uint32_t)(arow * SS + aseg) * 4;
    // B: tid<128 -> W1 tile, else W3 tile; row = (tid&127)>>1 (64 rows)
    const int brow = (tid & 127) >> 1, bseg = (tid & 1) * 16;
    const float* bSrc = ((tid < 128) ? W1 : W3) + (size_t)(n0 + brow) * DIM + bseg;
    const uint32_t bDstB = (uint32_t)(((tid < 128) ? 128 * SS : 192 * SS) + brow * SS + bseg) * 4;

    const int lane = tid & 31, warp = tid >> 5;
    const int wm = warp >> 1, wn = warp & 1;   // 4 x 2 warps, warp tile 32x32 (x2 matrices)
    const int gid = lane >> 2, tig = lane & 3;

    float acc1[2][4][4], acc3[2][4][4];
#pragma unroll
    for (int i = 0; i < 2; i++)
#pragma unroll
        for (int j = 0; j < 4; j++)
#pragma unroll
            for (int k = 0; k < 4; k++) { acc1[i][j][k] = 0.f; acc3[i][j][k] = 0.f; }

#define ISSUE_A(kk) do {                                              \
        int _s = (kk) % 3;                                            \
        uint32_t _b = sb + (uint32_t)(_s * STG_FLOATS) * 4;           \
        const float* _ga = aSrc + (kk) * 32;                          \
        const float* _gb = bSrc + (kk) * 32;                          \
        cp16(_b + aDstB +  0, _ga +  0); cp16(_b + aDstB + 16, _ga + 4);  \
        cp16(_b + aDstB + 32, _ga +  8); cp16(_b + aDstB + 48, _ga + 12); \
        cp16(_b + bDstB +  0, _gb +  0); cp16(_b + bDstB + 16, _gb + 4);  \
        cp16(_b + bDstB + 32, _gb +  8); cp16(_b + bDstB + 48, _gb + 12); \
        CP_COMMIT();                                                  \
    } while (0)

    ISSUE_A(0);
    ISSUE_A(1);

    const int KITER = DIM / 32;
    for (int kk = 0; kk < KITER; kk++) {
        CP_WAIT1();
        __syncthreads();
        if (kk + 2 < KITER) { ISSUE_A(kk + 2); } else { CP_COMMIT(); }

        const float* base = smf + (kk % 3) * STG_FLOATS;
        const float* Ab  = base + (wm * 32) * SS;
        const float* B1b = base + 128 * SS + (wn * 32) * SS;
        const float* B3b = base + 192 * SS + (wn * 32) * SS;
#pragma unroll
        for (int ks = 0; ks < 4; ks++) {
            const int k0 = ks * 8 + tig;
            uint32_t af[2][4], b1f[4][2], b3f[4][2];
#pragma unroll
            for (int mt = 0; mt < 2; mt++) {
                const float* ap = Ab + (mt * 16 + gid) * SS + k0;
                af[mt][0] = f2tf32(ap[0]);
                af[mt][1] = f2tf32(ap[8 * SS]);
                af[mt][2] = f2tf32(ap[4]);
                af[mt][3] = f2tf32(ap[8 * SS + 4]);
            }
#pragma unroll
            for (int nt = 0; nt < 4; nt++) {
                const float* bp1 = B1b + (nt * 8 + gid) * SS + k0;
                const float* bp3 = B3b + (nt * 8 + gid) * SS + k0;
                b1f[nt][0] = f2tf32(bp1[0]); b1f[nt][1] = f2tf32(bp1[4]);
                b3f[nt][0] = f2tf32(bp3[0]); b3f[nt][1] = f2tf32(bp3[4]);
            }
#pragma unroll
            for (int mt = 0; mt < 2; mt++)
#pragma unroll
                for (int nt = 0; nt < 4; nt++) {
                    mma_tf32(acc1[mt][nt], af[mt], b1f[nt]);
                    mma_tf32(acc3[mt][nt], af[mt], b3f[nt]);
                }
        }
    }

    // epilogue: act = silu(h1) * h3 -> g_act
#pragma unroll
    for (int mt = 0; mt < 2; mt++) {
#pragma unroll
        for (int h = 0; h < 2; h++) {
            const int m = m0 + wm * 32 + mt * 16 + gid + h * 8;
            if (m >= cnt) continue;
            float* dst = &g_act[((size_t)e * T_TOK + m) * INTER + n0 + wn * 32];
#pragma unroll
            for (int nt = 0; nt < 4; nt++) {
                float v0 = acc1[mt][nt][h * 2 + 0], u0 = acc3[mt][nt][h * 2 + 0];
                float v1 = acc1[mt][nt][h * 2 + 1], u1 = acc3[mt][nt][h * 2 + 1];
                *(float2*)(dst + nt * 8 + tig * 2) =
                    make_float2((v0 / (1.f + __expf(-v0))) * u0,
                                (v1 / (1.f + __expf(-v1))) * u1);
            }
        }
    }
#undef ISSUE_A
}

// =====================================================================
// stage B: y = act @ W2^T (* route weight), cp.async pipelined
// grid (16, DIM/128=8, 17), block 256 (8 warps as 2x4). M=128 N=128 BK=32.
// =====================================================================
__global__ __launch_bounds__(256, 2) void ffn_out_mma(
    const float* __restrict__ w2, const float* __restrict__ ws2,
    float* __restrict__ out)
{
    const int e   = blockIdx.z;
    const int cnt = (e == NEXP) ? T_TOK : g_cnt[e];
    const int m0  = blockIdx.x * 128;
    if (m0 >= cnt) return;
    const int n0  = blockIdx.y * 128;

    const float* W2 = (e == NEXP) ? ws2 : w2 + (size_t)e * DIM * INTER;

    extern __shared__ float smf[];
    const uint32_t sb = smem_u32(smf);
    const int tid = threadIdx.x;

    const int arow = tid >> 1, aseg = (tid & 1) * 16;
    int aidx = m0 + arow; if (aidx > cnt - 1) aidx = cnt - 1;
    const float* aSrc = g_act + ((size_t)e * T_TOK + aidx) * INTER + aseg;
    const uint32_t aDstB = (uint32_t)(arow * SS + aseg) * 4;
    const float* bSrc = W2 + (size_t)(n0 + arow) * INTER + aseg;
    const uint32_t bDstB = (uint32_t)(128 * SS + arow * SS + aseg) * 4;

    const int lane = tid & 31, warp = tid >> 5;
    const int wm = warp >> 2, wn = warp & 3;   // 2 x 4 warps, warp tile 64x32
    const int gid = lane >> 2, tig = lane & 3;

    float acc[4][4][4];
#pragma unroll
    for (int i = 0; i < 4; i++)
#pragma unroll
        for (int j = 0; j < 4; j++)
#pragma unroll
            for (int k = 0; k < 4; k++) acc[i][j][k] = 0.f;

#define ISSUE_B(kk) do {                                              \
        int _s = (kk) % 3;                                            \
        uint32_t _b = sb + (uint32_t)(_s * STG_FLOATS) * 4;           \
        const float* _ga = aSrc + (kk) * 32;                          \
        const float* _gb = bSrc + (kk) * 32;                          \
        cp16(_b + aDstB +  0, _ga +  0); cp16(_b + aDstB + 16, _ga + 4);  \
        cp16(_b + aDstB + 32, _ga +  8); cp16(_b + aDstB + 48, _ga + 12); \
        cp16(_b + bDstB +  0, _gb +  0); cp16(_b + bDstB + 16, _gb + 4);  \
        cp16(_b + bDstB + 32, _gb +  8); cp16(_b + bDstB + 48, _gb + 12); \
        CP_COMMIT();                                                  \
    } while (0)

    ISSUE_B(0);
    ISSUE_B(1);

    const int KITER = INTER / 32;
    for (int kk = 0; kk < KITER; kk++) {
        CP_WAIT1();
        __syncthreads();
        if (kk + 2 < KITER) { ISSUE_B(kk + 2); } else { CP_COMMIT(); }

        const float* base = smf + (kk % 3) * STG_FLOATS;
        const float* Ab = base + (wm * 64) * SS;
        const float* Bb = base + 128 * SS + (wn * 32) * SS;
#pragma unroll
        for (int ks = 0; ks < 4; ks++) {
            const int k0 = ks * 8 + tig;
            uint32_t af[4][4], bf[4][2];
#pragma unroll
            for (int mt = 0; mt < 4; mt++) {
                const float* ap = Ab + (mt * 16 + gid) * SS + k0;
                af[mt][0] = f2tf32(ap[0]);
                af[mt][1] = f2tf32(ap[8 * SS]);
                af[mt][2] = f2tf32(ap[4]);
                af[mt][3] = f2tf32(ap[8 * SS + 4]);
            }
#pragma unroll
            for (int nt = 0; nt < 4; nt++) {
                const float* bp = Bb + (nt * 8 + gid) * SS + k0;
                bf[nt][0] = f2tf32(bp[0]);
                bf[nt][1] = f2tf32(bp[4]);
            }
#pragma unroll
            for (int mt = 0; mt < 4; mt++)
#pragma unroll
                for (int nt = 0; nt < 4; nt++)
                    mma_tf32(acc[mt][nt], af[mt], bf[nt]);
        }
    }

    // epilogue
#pragma unroll
    for (int mt = 0; mt < 4; mt++) {
#pragma unroll
        for (int h = 0; h < 2; h++) {
            const int m = m0 + wm * 64 + mt * 16 + gid + h * 8;
            if (m >= cnt) continue;
            float wt = 1.f;
            float* dst;
            if (e == NEXP) {
                dst = out + (size_t)m * DIM + n0;
            } else {
                const int tokm = g_tok[e][m];
                const int sl   = g_slot[e][m];
                wt             = g_wt[e][m];
                dst = &g_ybuf[sl][(size_t)tokm * DIM + n0];
            }
#pragma unroll
            for (int nt = 0; nt < 4; nt++) {
                *(float2*)(dst + wn * 32 + nt * 8 + tig * 2) =
                    make_float2(acc[mt][nt][h * 2 + 0] * wt,
                                acc[mt][nt][h * 2 + 1] * wt);
            }
        }
    }
#undef ISSUE_B
}

// ---------------- reduce: out += sum_k ybuf[k] ----------------
__global__ void reduce_kernel(float* __restrict__ out) {
    size_t idx = ((size_t)blockIdx.x * blockDim.x + threadIdx.x) * 4;
    if (idx < (size_t)T_TOK * DIM) {
        float4 o = *(float4*)(out + idx);
        float4 a = *(const float4*)(&g_ybuf[0][idx]);
        float4 b = *(const float4*)(&g_ybuf[1][idx]);
        float4 c = *(const float4*)(&g_ybuf[2][idx]);
        float4 d = *(const float4*)(&g_ybuf[3][idx]);
        o.x += a.x + b.x + c.x + d.x;
        o.y += a.y + b.y + c.y + d.y;
        o.z += a.z + b.z + c.z + d.z;
        o.w += a.w + b.w + c.w + d.w;
        *(float4*)(out + idx) = o;
    }
}

// ---------------- launch ----------------
extern "C" void kernel_launch(void* const* d_in, const int* in_sizes, int n_in,
                              void* d_out, int out_size) {
    const float* x   = (const float*)d_in[0];
    const float* gw  = (const float*)d_in[1];
    const float* gb  = (const float*)d_in[2];
    const float* w1  = (const float*)d_in[3];
    const float* w2  = (const float*)d_in[4];
    const float* w3  = (const float*)d_in[5];
    const float* ws1 = (const float*)d_in[6];
    const float* ws2 = (const float*)d_in[7];
    const float* ws3 = (const float*)d_in[8];
    float* out = (float*)d_out;

    cudaFuncSetAttribute(ffn_in_mma,  cudaFuncAttributeMaxDynamicSharedMemorySize, SMEM_BYTES);
    cudaFuncSetAttribute(ffn_out_mma, cudaFuncAttributeMaxDynamicSharedMemorySize, SMEM_BYTES);

    init_kernel<<<1, 32>>>();
    gate_kernel<<<T_TOK, 32>>>(x, gw, gb);
    ffn_in_mma<<<dim3(T_TOK / 128, INTER / 64, NE1), 256, SMEM_BYTES>>>(x, w1, w3, ws1, ws3);
    ffn_out_mma<<<dim3(T_TOK / 128, DIM / 128, NE1), 256, SMEM_BYTES>>>(w2, ws2, out);
    reduce_kernel<<<(T_TOK * DIM / 4 + 255) / 256, 256>>>(out);
}

// round 5
// speedup vs baseline: 2.5149x; 1.0827x over previous
#include <cuda_runtime.h>
#include <math.h>
#include <stdint.h>

#define T_TOK 2048
#define DIM   1024
#define INTER 512
#define NEXP  16
#define TOPK  4
#define NGRP  4
#define GSZ   4
#define NE1   (NEXP + 1)

#define SS 36                                  // smem row stride (floats)
#define STG_FLOATS (256 * SS)                  // one pipeline stage (A:128 + B:128 rows)
#define SMEM_BYTES (3 * STG_FLOATS * 4)        // 110592

// ---------------- scratch ----------------
__device__ int           g_cnt[NEXP];
__device__ int           g_tok[NEXP][T_TOK];
__device__ unsigned char g_slot[NEXP][T_TOK];
__device__ float         g_wt[NEXP][T_TOK];
__device__ float         g_xr[(size_t)T_TOK * DIM];            // tf32-rounded x, 8MB
__device__ float         g_act[(size_t)NE1 * T_TOK * INTER];   // tf32-rounded, 71.3 MB
__device__ float         g_ybuf[TOPK][(size_t)T_TOK * DIM];    // 32 MB

// ---------------- helpers ----------------
__device__ __forceinline__ uint32_t smem_u32(const void* p) {
    uint32_t a;
    asm("{ .reg .u64 t; cvta.to.shared.u64 t, %1; cvt.u32.u64 %0, t; }" : "=r"(a) : "l"(p));
    return a;
}
__device__ __forceinline__ float f2tf32f(float f) {
    uint32_t u;
    asm("cvt.rna.tf32.f32 %0, %1;" : "=r"(u) : "f"(f));
    return __uint_as_float(u);
}
__device__ __forceinline__ uint32_t u2tf32(uint32_t f) {
    uint32_t u;
    asm("cvt.rna.tf32.f32 %0, %1;" : "=r"(u) : "f"(__uint_as_float(f)));
    return u;
}
__device__ __forceinline__ void cp16(uint32_t dst, const void* src) {
    asm volatile("cp.async.ca.shared.global [%0], [%1], 16;" :: "r"(dst), "l"(src));
}
#define CP_COMMIT() asm volatile("cp.async.commit_group;")
#define CP_WAIT1()  asm volatile("cp.async.wait_group 1;")

__device__ __forceinline__ void ldsm4(uint32_t& r0, uint32_t& r1, uint32_t& r2, uint32_t& r3,
                                      uint32_t addr) {
    asm volatile("ldmatrix.sync.aligned.m8n8.x4.shared.b16 {%0,%1,%2,%3}, [%4];"
                 : "=r"(r0), "=r"(r1), "=r"(r2), "=r"(r3) : "r"(addr));
}
__device__ __forceinline__ void mma_tf32(float* d, const uint32_t* a, uint32_t b0, uint32_t b1) {
    asm volatile(
        "mma.sync.aligned.m16n8k8.row.col.f32.tf32.tf32.f32 "
        "{%0,%1,%2,%3}, {%4,%5,%6,%7}, {%8,%9}, {%0,%1,%2,%3};"
        : "+f"(d[0]), "+f"(d[1]), "+f"(d[2]), "+f"(d[3])
        : "r"(a[0]), "r"(a[1]), "r"(a[2]), "r"(a[3]), "r"(b0), "r"(b1));
}

// ---------------- init ----------------
__global__ void init_kernel() {
    int i = threadIdx.x;
    if (i < NEXP) g_cnt[i] = 0;
}

// ---------------- gate: 8 warps/block, 1 warp per token; also emits rounded x ----
__global__ __launch_bounds__(256) void gate_kernel(const float* __restrict__ x,
                                                   const float* __restrict__ gw,
                                                   const float* __restrict__ gbias) {
    int t    = blockIdx.x * 8 + (threadIdx.x >> 5);
    int lane = threadIdx.x & 31;

    float xr[32];
    const float* xp = x + (size_t)t * DIM;
    float* xo = g_xr + (size_t)t * DIM;
#pragma unroll
    for (int i = 0; i < 32; i++) {
        xr[i] = xp[lane + i * 32];
        xo[lane + i * 32] = f2tf32f(xr[i]);
    }

    float sc[NEXP];
#pragma unroll
    for (int e = 0; e < NEXP; e++) {
        const float* w = gw + (size_t)e * DIM;
        float acc = 0.f;
#pragma unroll
        for (int i = 0; i < 32; i++) acc += xr[i] * w[lane + i * 32];
#pragma unroll
        for (int o = 16; o > 0; o >>= 1) acc += __shfl_xor_sync(0xffffffffu, acc, o);
        sc[e] = 1.f / (1.f + expf(-acc));
    }
    if (lane == 0) {
        float s[NEXP];
#pragma unroll
        for (int e = 0; e < NEXP; e++) s[e] = sc[e] + gbias[e];
        float gm[NGRP];
#pragma unroll
        for (int g = 0; g < NGRP; g++) {
            float m = s[g * GSZ];
#pragma unroll
            for (int j = 1; j < GSZ; j++) m = fmaxf(m, s[g * GSZ + j]);
            gm[g] = m;
        }
        int g1 = 0;
#pragma unroll
        for (int g = 1; g < NGRP; g++) if (gm[g] > gm[g1]) g1 = g;
        int g2 = -1;
#pragma unroll
        for (int g = 0; g < NGRP; g++) {
            if (g == g1) continue;
            if (g2 < 0 || gm[g] > gm[g2]) g2 = g;
        }
        float sm[NEXP];
#pragma unroll
        for (int e = 0; e < NEXP; e++) {
            int g = e / GSZ;
            sm[e] = (g == g1 || g == g2) ? s[e] : -1e30f;
        }
#pragma unroll
        for (int k = 0; k < TOPK; k++) {
            int best = 0; float bv = -1e38f;
#pragma unroll
            for (int e = 0; e < NEXP; e++) if (sm[e] > bv) { bv = sm[e]; best = e; }
            sm[best] = -1e38f;
            int pos = atomicAdd(&g_cnt[best], 1);
            g_tok[best][pos]  = t;
            g_slot[best][pos] = (unsigned char)k;
            g_wt[best][pos]   = sc[best];
        }
    }
}

// =====================================================================
// stage A: act = silu(X@W1^T) * (X@W3^T)  — ldmatrix + cp.async
// grid (16, INTER/64=8, 17), block 256 (8 warps as 4x2).
// Tile: M=128, N=64 (both W1 & W3), BK=32, 3-stage pipeline.
// smem stage: A 128 rows | B1 64 rows | B3 64 rows (SS floats each).
// =====================================================================
__global__ __launch_bounds__(256, 2) void ffn_in_mma(
    const float* __restrict__ w1, const float* __restrict__ w3,
    const float* __restrict__ ws1, const float* __restrict__ ws3)
{
    const int e   = blockIdx.z;
    const int cnt = (e == NEXP) ? T_TOK : g_cnt[e];
    const int m0  = blockIdx.x * 128;
    if (m0 >= cnt) return;
    const int n0  = blockIdx.y * 64;

    const float* W1 = (e == NEXP) ? ws1 : w1 + (size_t)e * INTER * DIM;
    const float* W3 = (e == NEXP) ? ws3 : w3 + (size_t)e * INTER * DIM;

    extern __shared__ float smf[];
    const uint32_t sb = smem_u32(smf);
    const int tid = threadIdx.x;

    // copy assignments
    const int arow = tid >> 1, aseg = (tid & 1) * 16;
    int aidx = m0 + arow; if (aidx > cnt - 1) aidx = cnt - 1;
    const int tok = (e == NEXP) ? (m0 + arow) : g_tok[e][aidx];
    const float* aSrc = g_xr + (size_t)tok * DIM + aseg;
    const uint32_t aDstB = (uint32_t)(arow * SS + aseg) * 4;
    const int brow = (tid & 127) >> 1, bseg = (tid & 1) * 16;
    const float* bSrc = ((tid < 128) ? W1 : W3) + (size_t)(n0 + brow) * DIM + bseg;
    const uint32_t bDstB = (uint32_t)(((tid < 128) ? 128 * SS : 192 * SS) + brow * SS + bseg) * 4;

    const int lane = tid & 31, warp = tid >> 5;
    const int wm = warp >> 1, wn = warp & 1;   // 4x2; warp tile: A 32 rows, 32 cols of each W
    const int gid = lane >> 2, tig = lane & 3;

    // LDSM per-thread offsets (floats)
    const uint32_t aLdsmOff = (uint32_t)((lane & 15) * SS + (lane >> 4) * 4);
    const uint32_t bLdsmOff = (uint32_t)((lane & 7) * SS + (lane >> 3) * 4);

    float acc1[2][4][4], acc3[2][4][4];
#pragma unroll
    for (int i = 0; i < 2; i++)
#pragma unroll
        for (int j = 0; j < 4; j++)
#pragma unroll
            for (int k = 0; k < 4; k++) { acc1[i][j][k] = 0.f; acc3[i][j][k] = 0.f; }

#define ISSUE_A(kk) do {                                              \
        uint32_t _b = sb + (uint32_t)(((kk) % 3) * STG_FLOATS) * 4;   \
        const float* _ga = aSrc + (kk) * 32;                          \
        const float* _gb = bSrc + (kk) * 32;                          \
        cp16(_b + aDstB +  0, _ga +  0); cp16(_b + aDstB + 16, _ga + 4);  \
        cp16(_b + aDstB + 32, _ga +  8); cp16(_b + aDstB + 48, _ga + 12); \
        cp16(_b + bDstB +  0, _gb +  0); cp16(_b + bDstB + 16, _gb + 4);  \
        cp16(_b + bDstB + 32, _gb +  8); cp16(_b + bDstB + 48, _gb + 12); \
        CP_COMMIT();                                                  \
    } while (0)

    ISSUE_A(0);
    ISSUE_A(1);

    const int KITER = DIM / 32;
    for (int kk = 0; kk < KITER; kk++) {
        CP_WAIT1();
        __syncthreads();
        if (kk + 2 < KITER) { ISSUE_A(kk + 2); } else { CP_COMMIT(); }

        const uint32_t stage = sb + (uint32_t)((kk % 3) * STG_FLOATS) * 4;
        const uint32_t Ab  = stage + ((uint32_t)(wm * 32) * SS + aLdsmOff) * 4;
        const uint32_t B1b = stage + ((uint32_t)(128 * SS) + (uint32_t)(wn * 32) * SS + bLdsmOff) * 4;
        const uint32_t B3b = stage + ((uint32_t)(192 * SS) + (uint32_t)(wn * 32) * SS + bLdsmOff) * 4;

#pragma unroll
        for (int kp = 0; kp < 2; kp++) {     // k-pair: covers ks = 2kp, 2kp+1
            // A fragments: 2 mtiles x 2 ks
            uint32_t af[2][2][4];
#pragma unroll
            for (int mt = 0; mt < 2; mt++)
#pragma unroll
                for (int k2 = 0; k2 < 2; k2++)
                    ldsm4(af[mt][k2][0], af[mt][k2][1], af[mt][k2][2], af[mt][k2][3],
                          Ab + ((uint32_t)(mt * 16) * SS + (uint32_t)(kp * 2 + k2) * 8) * 4);
            // B fragments per ntile (x4 = two ks), cvt to tf32, MMA immediately
#pragma unroll
            for (int nt = 0; nt < 4; nt++) {
                uint32_t b0, b1, b2, b3;
                ldsm4(b0, b1, b2, b3, B1b + ((uint32_t)(nt * 8) * SS + (uint32_t)(kp * 16)) * 4);
                b0 = u2tf32(b0); b1 = u2tf32(b1); b2 = u2tf32(b2); b3 = u2tf32(b3);
#pragma unroll
                for (int mt = 0; mt < 2; mt++) {
                    mma_tf32(acc1[mt][nt], af[mt][0], b0, b1);
                    mma_tf32(acc1[mt][nt], af[mt][1], b2, b3);
                }
                ldsm4(b0, b1, b2, b3, B3b + ((uint32_t)(nt * 8) * SS + (uint32_t)(kp * 16)) * 4);
                b0 = u2tf32(b0); b1 = u2tf32(b1); b2 = u2tf32(b2); b3 = u2tf32(b3);
#pragma unroll
                for (int mt = 0; mt < 2; mt++) {
                    mma_tf32(acc3[mt][nt], af[mt][0], b0, b1);
                    mma_tf32(acc3[mt][nt], af[mt][1], b2, b3);
                }
            }
        }
    }

    // epilogue: act = silu(h1) * h3, tf32-rounded -> g_act
#pragma unroll
    for (int mt = 0; mt < 2; mt++) {
#pragma unroll
        for (int h = 0; h < 2; h++) {
            const int m = m0 + wm * 32 + mt * 16 + gid + h * 8;
            if (m >= cnt) continue;
            float* dst = &g_act[((size_t)e * T_TOK + m) * INTER + n0 + wn * 32];
#pragma unroll
            for (int nt = 0; nt < 4; nt++) {
                float v0 = acc1[mt][nt][h * 2 + 0], u0 = acc3[mt][nt][h * 2 + 0];
                float v1 = acc1[mt][nt][h * 2 + 1], u1 = acc3[mt][nt][h * 2 + 1];
                *(float2*)(dst + nt * 8 + tig * 2) =
                    make_float2(f2tf32f((v0 / (1.f + __expf(-v0))) * u0),
                                f2tf32f((v1 / (1.f + __expf(-v1))) * u1));
            }
        }
    }
#undef ISSUE_A
}

// =====================================================================
// stage B: y = act @ W2^T (* weight) — ldmatrix + cp.async
// grid (16, DIM/128=8, 17), block 256 (8 warps as 2x4). M=128 N=128 BK=32.
// =====================================================================
__global__ __launch_bounds__(256, 2) void ffn_out_mma(
    const float* __restrict__ w2, const float* __restrict__ ws2,
    float* __restrict__ out)
{
    const int e   = blockIdx.z;
    const int cnt = (e == NEXP) ? T_TOK : g_cnt[e];
    const int m0  = blockIdx.x * 128;
    if (m0 >= cnt) return;
    const int n0  = blockIdx.y * 128;

    const float* W2 = (e == NEXP) ? ws2 : w2 + (size_t)e * DIM * INTER;

    extern __shared__ float smf[];
    const uint32_t sb = smem_u32(smf);
    const int tid = threadIdx.x;

    const int arow = tid >> 1, aseg = (tid & 1) * 16;
    int aidx = m0 + arow; if (aidx > cnt - 1) aidx = cnt - 1;
    const float* aSrc = g_act + ((size_t)e * T_TOK + aidx) * INTER + aseg;
    const uint32_t aDstB = (uint32_t)(arow * SS + aseg) * 4;
    const float* bSrc = W2 + (size_t)(n0 + arow) * INTER + aseg;
    const uint32_t bDstB = (uint32_t)(128 * SS + arow * SS + aseg) * 4;

    const int lane = tid & 31, warp = tid >> 5;
    const int wm = warp >> 2, wn = warp & 3;   // 2x4; warp tile 64x32
    const int gid = lane >> 2, tig = lane & 3;

    const uint32_t aLdsmOff = (uint32_t)((lane & 15) * SS + (lane >> 4) * 4);
    const uint32_t bLdsmOff = (uint32_t)((lane & 7) * SS + (lane >> 3) * 4);

    float acc[4][4][4];
#pragma unroll
    for (int i = 0; i < 4; i++)
#pragma unroll
        for (int j = 0; j < 4; j++)
#pragma unroll
            for (int k = 0; k < 4; k++) acc[i][j][k] = 0.f;

#define ISSUE_B(kk) do {                                              \
        uint32_t _b = sb + (uint32_t)(((kk) % 3) * STG_FLOATS) * 4;   \
        const float* _ga = aSrc + (kk) * 32;                          \
        const float* _gb = bSrc + (kk) * 32;                          \
        cp16(_b + aDstB +  0, _ga +  0); cp16(_b + aDstB + 16, _ga + 4);  \
        cp16(_b + aDstB + 32, _ga +  8); cp16(_b + aDstB + 48, _ga + 12); \
        cp16(_b + bDstB +  0, _gb +  0); cp16(_b + bDstB + 16, _gb + 4);  \
        cp16(_b + bDstB + 32, _gb +  8); cp16(_b + bDstB + 48, _gb + 12); \
        CP_COMMIT();                                                  \
    } while (0)

    ISSUE_B(0);
    ISSUE_B(1);

    const int KITER = INTER / 32;
    for (int kk = 0; kk < KITER; kk++) {
        CP_WAIT1();
        __syncthreads();
        if (kk + 2 < KITER) { ISSUE_B(kk + 2); } else { CP_COMMIT(); }

        const uint32_t stage = sb + (uint32_t)((kk % 3) * STG_FLOATS) * 4;
        const uint32_t Ab = stage + ((uint32_t)(wm * 64) * SS + aLdsmOff) * 4;
        const uint32_t Bb = stage + ((uint32_t)(128 * SS) + (uint32_t)(wn * 32) * SS + bLdsmOff) * 4;

#pragma unroll
        for (int kp = 0; kp < 2; kp++) {
            uint32_t af[4][2][4];
#pragma unroll
            for (int mt = 0; mt < 4; mt++)
#pragma unroll
                for (int k2 = 0; k2 < 2; k2++)
                    ldsm4(af[mt][k2][0], af[mt][k2][1], af[mt][k2][2], af[mt][k2][3],
                          Ab + ((uint32_t)(mt * 16) * SS + (uint32_t)(kp * 2 + k2) * 8) * 4);
#pragma unroll
            for (int nt = 0; nt < 4; nt++) {
                uint32_t b0, b1, b2, b3;
                ldsm4(b0, b1, b2, b3, Bb + ((uint32_t)(nt * 8) * SS + (uint32_t)(kp * 16)) * 4);
                b0 = u2tf32(b0); b1 = u2tf32(b1); b2 = u2tf32(b2); b3 = u2tf32(b3);
#pragma unroll
                for (int mt = 0; mt < 4; mt++) {
                    mma_tf32(acc[mt][nt], af[mt][0], b0, b1);
                    mma_tf32(acc[mt][nt], af[mt][1], b2, b3);
                }
            }
        }
    }

    // epilogue
#pragma unroll
    for (int mt = 0; mt < 4; mt++) {
#pragma unroll
        for (int h = 0; h < 2; h++) {
            const int m = m0 + wm * 64 + mt * 16 + gid + h * 8;
            if (m >= cnt) continue;
            float wt = 1.f;
            float* dst;
            if (e == NEXP) {
                dst = out + (size_t)m * DIM + n0;
            } else {
                const int tokm = g_tok[e][m];
                const int sl   = g_slot[e][m];
                wt             = g_wt[e][m];
                dst = &g_ybuf[sl][(size_t)tokm * DIM + n0];
            }
#pragma unroll
            for (int nt = 0; nt < 4; nt++) {
                *(float2*)(dst + wn * 32 + nt * 8 + tig * 2) =
                    make_float2(acc[mt][nt][h * 2 + 0] * wt,
                                acc[mt][nt][h * 2 + 1] * wt);
            }
        }
    }
#undef ISSUE_B
}

// ---------------- reduce ----------------
__global__ void reduce_kernel(float* __restrict__ out) {
    size_t idx = ((size_t)blockIdx.x * blockDim.x + threadIdx.x) * 4;
    if (idx < (size_t)T_TOK * DIM) {
        float4 o = *(float4*)(out + idx);
        float4 a = *(const float4*)(&g_ybuf[0][idx]);
        float4 b = *(const float4*)(&g_ybuf[1][idx]);
        float4 c = *(const float4*)(&g_ybuf[2][idx]);
        float4 d = *(const float4*)(&g_ybuf[3][idx]);
        o.x += a.x + b.x + c.x + d.x;
        o.y += a.y + b.y + c.y + d.y;
        o.z += a.z + b.z + c.z + d.z;
        o.w += a.w + b.w + c.w + d.w;
        *(float4*)(out + idx) = o;
    }
}

// ---------------- launch ----------------
extern "C" void kernel_launch(void* const* d_in, const int* in_sizes, int n_in,
                              void* d_out, int out_size) {
    const float* x   = (const float*)d_in[0];
    const float* gw  = (const float*)d_in[1];
    const float* gb  = (const float*)d_in[2];
    const float* w1  = (const float*)d_in[3];
    const float* w2  = (const float*)d_in[4];
    const float* w3  = (const float*)d_in[5];
    const float* ws1 = (const float*)d_in[6];
    const float* ws2 = (const float*)d_in[7];
    const float* ws3 = (const float*)d_in[8];
    float* out = (float*)d_out;

    cudaFuncSetAttribute(ffn_in_mma,  cudaFuncAttributeMaxDynamicSharedMemorySize, SMEM_BYTES);
    cudaFuncSetAttribute(ffn_out_mma, cudaFuncAttributeMaxDynamicSharedMemorySize, SMEM_BYTES);

    init_kernel<<<1, 32>>>();
    gate_kernel<<<T_TOK / 8, 256>>>(x, gw, gb);
    ffn_in_mma<<<dim3(T_TOK / 128, INTER / 64, NE1), 256, SMEM_BYTES>>>(w1, w3, ws1, ws3);
    ffn_out_mma<<<dim3(T_TOK / 128, DIM / 128, NE1), 256, SMEM_BYTES>>>(w2, ws2, out);
    reduce_kernel<<<(T_TOK * DIM / 4 + 255) / 256, 256>>>(out);
}

// round 6
// speedup vs baseline: 4.1150x; 1.6362x over previous
#include <cuda_runtime.h>
#include <cuda_fp16.h>
#include <math.h>
#include <stdint.h>

#define T_TOK 2048
#define DIM   1024
#define INTER 512
#define NEXP  16
#define TOPK  4
#define NGRP  4
#define GSZ   4
#define NE1   (NEXP + 1)

#define RB        144                    // smem row stride, bytes (128B data + 16B pad)
#define STG_BYTES (256 * RB)             // one stage: 256 rows
#define SMEM_BYTES (3 * STG_BYTES)       // 110592

#define WBIG  ((size_t)NEXP * INTER * DIM)   // 8388608
#define WSML  ((size_t)INTER * DIM)          // 524288

// ---------------- scratch ----------------
__device__ int           g_cnt[NEXP];
__device__ int           g_tok[NEXP][T_TOK];
__device__ unsigned char g_slot[NEXP][T_TOK];
__device__ float         g_wt[NEXP][T_TOK];
__device__ __half        g_xrh[(size_t)T_TOK * DIM];             // 4 MB
__device__ __half        g_acth[(size_t)NE1 * T_TOK * INTER];    // 35.7 MB
__device__ float         g_ybuf[TOPK][(size_t)T_TOK * DIM];      // 32 MB
// fp16 weights; slot e==NEXP holds the shared expert
__device__ __half        g_w1h[WBIG + WSML];
__device__ __half        g_w3h[WBIG + WSML];
__device__ __half        g_w2h[WBIG + WSML];

// ---------------- helpers ----------------
__device__ __forceinline__ uint32_t smem_u32(const void* p) {
    uint32_t a;
    asm("{ .reg .u64 t; cvta.to.shared.u64 t, %1; cvt.u32.u64 %0, t; }" : "=r"(a) : "l"(p));
    return a;
}
__device__ __forceinline__ void cp16(uint32_t dst, const void* src) {
    asm volatile("cp.async.ca.shared.global [%0], [%1], 16;" :: "r"(dst), "l"(src));
}
#define CP_COMMIT() asm volatile("cp.async.commit_group;")
#define CP_WAIT1()  asm volatile("cp.async.wait_group 1;")

__device__ __forceinline__ void ldsm4(uint32_t& r0, uint32_t& r1, uint32_t& r2, uint32_t& r3,
                                      uint32_t addr) {
    asm volatile("ldmatrix.sync.aligned.m8n8.x4.shared.b16 {%0,%1,%2,%3}, [%4];"
                 : "=r"(r0), "=r"(r1), "=r"(r2), "=r"(r3) : "r"(addr));
}
__device__ __forceinline__ void mma_f16(float* d, const uint32_t* a, uint32_t b0, uint32_t b1) {
    asm volatile(
        "mma.sync.aligned.m16n8k16.row.col.f32.f16.f16.f32 "
        "{%0,%1,%2,%3}, {%4,%5,%6,%7}, {%8,%9}, {%0,%1,%2,%3};"
        : "+f"(d[0]), "+f"(d[1]), "+f"(d[2]), "+f"(d[3])
        : "r"(a[0]), "r"(a[1]), "r"(a[2]), "r"(a[3]), "r"(b0), "r"(b1));
}

// ---------------- init ----------------
__global__ void init_kernel() {
    int i = threadIdx.x;
    if (i < NEXP) g_cnt[i] = 0;
}

// ---------------- weight conversion fp32 -> fp16 ----------------
__global__ __launch_bounds__(256) void convert_w(
    const float* __restrict__ w1, const float* __restrict__ w2, const float* __restrict__ w3,
    const float* __restrict__ ws1, const float* __restrict__ ws2, const float* __restrict__ ws3)
{
    const int seg = blockIdx.y;
    const size_t n = (seg < 3) ? WBIG : WSML;
    const size_t i = ((size_t)blockIdx.x * 256 + threadIdx.x) * 8;
    if (i >= n) return;
    const float* src; __half* dst;
    switch (seg) {
        case 0: src = w1;  dst = g_w1h;        break;
        case 1: src = w3;  dst = g_w3h;        break;
        case 2: src = w2;  dst = g_w2h;        break;
        case 3: src = ws1; dst = g_w1h + WBIG; break;
        case 4: src = ws3; dst = g_w3h + WBIG; break;
        default: src = ws2; dst = g_w2h + WBIG; break;
    }
    float4 a = *(const float4*)(src + i);
    float4 b = *(const float4*)(src + i + 4);
    __half2 h0 = __floats2half2_rn(a.x, a.y), h1 = __floats2half2_rn(a.z, a.w);
    __half2 h2 = __floats2half2_rn(b.x, b.y), h3 = __floats2half2_rn(b.z, b.w);
    uint4 o;
    o.x = *(uint32_t*)&h0; o.y = *(uint32_t*)&h1;
    o.z = *(uint32_t*)&h2; o.w = *(uint32_t*)&h3;
    *(uint4*)(dst + i) = o;
}

// ---------------- gate: 8 warps/block, 1 warp per token; emits fp16 x ----------------
__global__ __launch_bounds__(256) void gate_kernel(const float* __restrict__ x,
                                                   const float* __restrict__ gw,
                                                   const float* __restrict__ gbias) {
    int t    = blockIdx.x * 8 + (threadIdx.x >> 5);
    int lane = threadIdx.x & 31;

    float xr[32];
    const float* xp = x + (size_t)t * DIM;
    __half* xo = g_xrh + (size_t)t * DIM;
#pragma unroll
    for (int i = 0; i < 32; i++) {
        xr[i] = xp[lane + i * 32];
        xo[lane + i * 32] = __float2half_rn(xr[i]);
    }

    float sc[NEXP];
#pragma unroll
    for (int e = 0; e < NEXP; e++) {
        const float* w = gw + (size_t)e * DIM;
        float acc = 0.f;
#pragma unroll
        for (int i = 0; i < 32; i++) acc += xr[i] * w[lane + i * 32];
#pragma unroll
        for (int o = 16; o > 0; o >>= 1) acc += __shfl_xor_sync(0xffffffffu, acc, o);
        sc[e] = 1.f / (1.f + expf(-acc));
    }
    if (lane == 0) {
        float s[NEXP];
#pragma unroll
        for (int e = 0; e < NEXP; e++) s[e] = sc[e] + gbias[e];
        float gm[NGRP];
#pragma unroll
        for (int g = 0; g < NGRP; g++) {
            float m = s[g * GSZ];
#pragma unroll
            for (int j = 1; j < GSZ; j++) m = fmaxf(m, s[g * GSZ + j]);
            gm[g] = m;
        }
        int g1 = 0;
#pragma unroll
        for (int g = 1; g < NGRP; g++) if (gm[g] > gm[g1]) g1 = g;
        int g2 = -1;
#pragma unroll
        for (int g = 0; g < NGRP; g++) {
            if (g == g1) continue;
            if (g2 < 0 || gm[g] > gm[g2]) g2 = g;
        }
        float sm[NEXP];
#pragma unroll
        for (int e = 0; e < NEXP; e++) {
            int g = e / GSZ;
            sm[e] = (g == g1 || g == g2) ? s[e] : -1e30f;
        }
#pragma unroll
        for (int k = 0; k < TOPK; k++) {
            int best = 0; float bv = -1e38f;
#pragma unroll
            for (int e = 0; e < NEXP; e++) if (sm[e] > bv) { bv = sm[e]; best = e; }
            sm[best] = -1e38f;
            int pos = atomicAdd(&g_cnt[best], 1);
            g_tok[best][pos]  = t;
            g_slot[best][pos] = (unsigned char)k;
            g_wt[best][pos]   = sc[best];
        }
    }
}

// =====================================================================
// stage A: act = silu(X@W1^T) * (X@W3^T)  — fp16 mma m16n8k16
// grid (16, INTER/64=8, 17), block 256 (8 warps 4x2). M=128, N=64 (x2), BK=64.
// stage layout: A rows 0-127 | W1 rows 128-191 | W3 rows 192-255 (RB bytes each)
// =====================================================================
__global__ __launch_bounds__(256, 2) void ffn_in_mma()
{
    const int e   = blockIdx.z;
    const int cnt = (e == NEXP) ? T_TOK : g_cnt[e];
    const int m0  = blockIdx.x * 128;
    if (m0 >= cnt) return;
    const int n0  = blockIdx.y * 64;

    extern __shared__ char smc[];
    const uint32_t sb = smem_u32(smc);
    const int tid = threadIdx.x;

    // copy assignments: each thread owns half a row (32 halfs = 64B = 4 cp16)
    const int arow = tid >> 1, aseg = (tid & 1) * 32;
    int aidx = m0 + arow; if (aidx > cnt - 1) aidx = cnt - 1;
    const int tok = (e == NEXP) ? (m0 + arow) : g_tok[e][aidx];
    const __half* aSrc = g_xrh + (size_t)tok * DIM + aseg;
    const uint32_t aDstB = (uint32_t)arow * RB + aseg * 2;
    const int brow = (tid & 127) >> 1, bseg = (tid & 1) * 32;
    const __half* bSrc = ((tid < 128) ? g_w1h : g_w3h)
                         + (size_t)e * INTER * DIM + (size_t)(n0 + brow) * DIM + bseg;
    const uint32_t bDstB = ((tid < 128) ? 128u : 192u) * RB + (uint32_t)brow * RB + bseg * 2;

    const int lane = tid & 31, warp = tid >> 5;
    const int wm = warp >> 1, wn = warp & 1;   // 4x2
    const int gid = lane >> 2, tig = lane & 3;

    const uint32_t aOff = (uint32_t)(lane & 15) * RB + (uint32_t)(lane >> 4) * 16;
    const uint32_t bOff = ((uint32_t)(lane & 7) + (uint32_t)((lane >> 4) & 1) * 8) * RB
                        + (uint32_t)((lane >> 3) & 1) * 16;

    float acc1[2][4][4], acc3[2][4][4];
#pragma unroll
    for (int i = 0; i < 2; i++)
#pragma unroll
        for (int j = 0; j < 4; j++)
#pragma unroll
            for (int k = 0; k < 4; k++) { acc1[i][j][k] = 0.f; acc3[i][j][k] = 0.f; }

#define ISSUE_A(kk) do {                                                  \
        uint32_t _b = sb + (uint32_t)(((kk) % 3) * STG_BYTES);            \
        const __half* _ga = aSrc + (kk) * 64;                             \
        const __half* _gb = bSrc + (kk) * 64;                             \
        cp16(_b + aDstB +  0, _ga +  0); cp16(_b + aDstB + 16, _ga +  8); \
        cp16(_b + aDstB + 32, _ga + 16); cp16(_b + aDstB + 48, _ga + 24); \
        cp16(_b + bDstB +  0, _gb +  0); cp16(_b + bDstB + 16, _gb +  8); \
        cp16(_b + bDstB + 32, _gb + 16); cp16(_b + bDstB + 48, _gb + 24); \
        CP_COMMIT();                                                      \
    } while (0)

    ISSUE_A(0);
    ISSUE_A(1);

    const int KITER = DIM / 64;
    for (int kk = 0; kk < KITER; kk++) {
        CP_WAIT1();
        __syncthreads();
        if (kk + 2 < KITER) { ISSUE_A(kk + 2); } else { CP_COMMIT(); }

        const uint32_t stage = sb + (uint32_t)((kk % 3) * STG_BYTES);
        const uint32_t Ab  = stage + (uint32_t)(wm * 32) * RB + aOff;
        const uint32_t B1b = stage + 128u * RB + (uint32_t)(wn * 32) * RB + bOff;
        const uint32_t B3b = stage + 192u * RB + (uint32_t)(wn * 32) * RB + bOff;

#pragma unroll
        for (int ks = 0; ks < 4; ks++) {
            const uint32_t kb = (uint32_t)ks * 32;
            uint32_t af[2][4];
#pragma unroll
            for (int mt = 0; mt < 2; mt++)
                ldsm4(af[mt][0], af[mt][1], af[mt][2], af[mt][3],
                      Ab + (uint32_t)(mt * 16) * RB + kb);
#pragma unroll
            for (int ntp = 0; ntp < 2; ntp++) {
                uint32_t b0, b1, b2, b3;
                ldsm4(b0, b1, b2, b3, B1b + (uint32_t)(ntp * 16) * RB + kb);
#pragma unroll
                for (int mt = 0; mt < 2; mt++) {
                    mma_f16(acc1[mt][2 * ntp + 0], af[mt], b0, b1);
                    mma_f16(acc1[mt][2 * ntp + 1], af[mt], b2, b3);
                }
                ldsm4(b0, b1, b2, b3, B3b + (uint32_t)(ntp * 16) * RB + kb);
#pragma unroll
                for (int mt = 0; mt < 2; mt++) {
                    mma_f16(acc3[mt][2 * ntp + 0], af[mt], b0, b1);
                    mma_f16(acc3[mt][2 * ntp + 1], af[mt], b2, b3);
                }
            }
        }
    }

    // epilogue: act = silu(h1) * h3 -> fp16 g_acth
#pragma unroll
    for (int mt = 0; mt < 2; mt++) {
#pragma unroll
        for (int h = 0; h < 2; h++) {
            const int m = m0 + wm * 32 + mt * 16 + gid + h * 8;
            if (m >= cnt) continue;
            __half* dst = &g_acth[((size_t)e * T_TOK + m) * INTER + n0 + wn * 32];
#pragma unroll
            for (int nt = 0; nt < 4; nt++) {
                float v0 = acc1[mt][nt][h * 2 + 0], u0 = acc3[mt][nt][h * 2 + 0];
                float v1 = acc1[mt][nt][h * 2 + 1], u1 = acc3[mt][nt][h * 2 + 1];
                *(__half2*)(dst + nt * 8 + tig * 2) =
                    __floats2half2_rn((v0 / (1.f + __expf(-v0))) * u0,
                                      (v1 / (1.f + __expf(-v1))) * u1);
            }
        }
    }
#undef ISSUE_A
}

// =====================================================================
// stage B: y = act @ W2^T (* weight) — fp16 mma m16n8k16
// grid (16, DIM/128=8, 17), block 256 (8 warps 2x4). M=128, N=128, BK=64.
// stage layout: A rows 0-127 | W2 rows 128-255
// =====================================================================
__global__ __launch_bounds__(256, 2) void ffn_out_mma(float* __restrict__ out)
{
    const int e   = blockIdx.z;
    const int cnt = (e == NEXP) ? T_TOK : g_cnt[e];
    const int m0  = blockIdx.x * 128;
    if (m0 >= cnt) return;
    const int n0  = blockIdx.y * 128;

    extern __shared__ char smc[];
    const uint32_t sb = smem_u32(smc);
    const int tid = threadIdx.x;

    const int arow = tid >> 1, aseg = (tid & 1) * 32;
    int aidx = m0 + arow; if (aidx > cnt - 1) aidx = cnt - 1;
    const __half* aSrc = g_acth + ((size_t)e * T_TOK + aidx) * INTER + aseg;
    const uint32_t aDstB = (uint32_t)arow * RB + aseg * 2;
    const __half* bSrc = g_w2h + (size_t)e * DIM * INTER + (size_t)(n0 + arow) * INTER + aseg;
    const uint32_t bDstB = 128u * RB + (uint32_t)arow * RB + aseg * 2;

    const int lane = tid & 31, warp = tid >> 5;
    const int wm = warp >> 2, wn = warp & 3;   // 2x4
    const int gid = lane >> 2, tig = lane & 3;

    const uint32_t aOff = (uint32_t)(lane & 15) * RB + (uint32_t)(lane >> 4) * 16;
    const uint32_t bOff = ((uint32_t)(lane & 7) + (uint32_t)((lane >> 4) & 1) * 8) * RB
                        + (uint32_t)((lane >> 3) & 1) * 16;

    float acc[4][4][4];
#pragma unroll
    for (int i = 0; i < 4; i++)
#pragma unroll
        for (int j = 0; j < 4; j++)
#pragma unroll
            for (int k = 0; k < 4; k++) acc[i][j][k] = 0.f;

#define ISSUE_B(kk) do {                                                  \
        uint32_t _b = sb + (uint32_t)(((kk) % 3) * STG_BYTES);            \
        const __half* _ga = aSrc + (kk) * 64;                             \
        const __half* _gb = bSrc + (kk) * 64;                             \
        cp16(_b + aDstB +  0, _ga +  0); cp16(_b + aDstB + 16, _ga +  8); \
        cp16(_b + aDstB + 32, _ga + 16); cp16(_b + aDstB + 48, _ga + 24); \
        cp16(_b + bDstB +  0, _gb +  0); cp16(_b + bDstB + 16, _gb +  8); \
        cp16(_b + bDstB + 32, _gb + 16); cp16(_b + bDstB + 48, _gb + 24); \
        CP_COMMIT();                                                      \
    } while (0)

    ISSUE_B(0);
    ISSUE_B(1);

    const int KITER = INTER / 64;
    for (int kk = 0; kk < KITER; kk++) {
        CP_WAIT1();
        __syncthreads();
        if (kk + 2 < KITER) { ISSUE_B(kk + 2); } else { CP_COMMIT(); }

        const uint32_t stage = sb + (uint32_t)((kk % 3) * STG_BYTES);
        const uint32_t Ab = stage + (uint32_t)(wm * 64) * RB + aOff;
        const uint32_t Bb = stage + 128u * RB + (uint32_t)(wn * 32) * RB + bOff;

#pragma unroll
        for (int ks = 0; ks < 4; ks++) {
            const uint32_t kb = (uint32_t)ks * 32;
            uint32_t af[4][4];
#pragma unroll
            for (int mt = 0; mt < 4; mt++)
                ldsm4(af[mt][0], af[mt][1], af[mt][2], af[mt][3],
                      Ab + (uint32_t)(mt * 16) * RB + kb);
#pragma unroll
            for (int ntp = 0; ntp < 2; ntp++) {
                uint32_t b0, b1, b2, b3;
                ldsm4(b0, b1, b2, b3, Bb + (uint32_t)(ntp * 16) * RB + kb);
#pragma unroll
                for (int mt = 0; mt < 4; mt++) {
                    mma_f16(acc[mt][2 * ntp + 0], af[mt], b0, b1);
                    mma_f16(acc[mt][2 * ntp + 1], af[mt], b2, b3);
                }
            }
        }
    }

    // epilogue
#pragma unroll
    for (int mt = 0; mt < 4; mt++) {
#pragma unroll
        for (int h = 0; h < 2; h++) {
            const int m = m0 + wm * 64 + mt * 16 + gid + h * 8;
            if (m >= cnt) continue;
            float wt = 1.f;
            float* dst;
            if (e == NEXP) {
                dst = out + (size_t)m * DIM + n0;
            } else {
                const int tokm = g_tok[e][m];
                const int sl   = g_slot[e][m];
                wt             = g_wt[e][m];
                dst = &g_ybuf[sl][(size_t)tokm * DIM + n0];
            }
#pragma unroll
            for (int nt = 0; nt < 4; nt++) {
                *(float2*)(dst + wn * 32 + nt * 8 + tig * 2) =
                    make_float2(acc[mt][nt][h * 2 + 0] * wt,
                                acc[mt][nt][h * 2 + 1] * wt);
            }
        }
    }
#undef ISSUE_B
}

// ---------------- reduce ----------------
__global__ void reduce_kernel(float* __restrict__ out) {
    size_t idx = ((size_t)blockIdx.x * blockDim.x + threadIdx.x) * 4;
    if (idx < (size_t)T_TOK * DIM) {
        float4 o = *(float4*)(out + idx);
        float4 a = *(const float4*)(&g_ybuf[0][idx]);
        float4 b = *(const float4*)(&g_ybuf[1][idx]);
        float4 c = *(const float4*)(&g_ybuf[2][idx]);
        float4 d = *(const float4*)(&g_ybuf[3][idx]);
        o.x += a.x + b.x + c.x + d.x;
        o.y += a.y + b.y + c.y + d.y;
        o.z += a.z + b.z + c.z + d.z;
        o.w += a.w + b.w + c.w + d.w;
        *(float4*)(out + idx) = o;
    }
}

// ---------------- launch ----------------
extern "C" void kernel_launch(void* const* d_in, const int* in_sizes, int n_in,
                              void* d_out, int out_size) {
    const float* x   = (const float*)d_in[0];
    const float* gw  = (const float*)d_in[1];
    const float* gb  = (const float*)d_in[2];
    const float* w1  = (const float*)d_in[3];
    const float* w2  = (const float*)d_in[4];
    const float* w3  = (const float*)d_in[5];
    const float* ws1 = (const float*)d_in[6];
    const float* ws2 = (const float*)d_in[7];
    const float* ws3 = (const float*)d_in[8];
    float* out = (float*)d_out;

    cudaFuncSetAttribute(ffn_in_mma,  cudaFuncAttributeMaxDynamicSharedMemorySize, SMEM_BYTES);
    cudaFuncSetAttribute(ffn_out_mma, cudaFuncAttributeMaxDynamicSharedMemorySize, SMEM_BYTES);

    init_kernel<<<1, 32>>>();
    convert_w<<<dim3(4096, 6), 256>>>(w1, w2, w3, ws1, ws2, ws3);
    gate_kernel<<<T_TOK / 8, 256>>>(x, gw, gb);
    ffn_in_mma<<<dim3(T_TOK / 128, INTER / 64, NE1), 256, SMEM_BYTES>>>();
    ffn_out_mma<<<dim3(T_TOK / 128, DIM / 128, NE1), 256, SMEM_BYTES>>>(out);
    reduce_kernel<<<(T_TOK * DIM / 4 + 255) / 256, 256>>>(out);
}

// round 7
// speedup vs baseline: 4.1960x; 1.0197x over previous
#include <cuda_runtime.h>
#include <cuda_fp16.h>
#include <math.h>
#include <stdint.h>

#define T_TOK 2048
#define DIM   1024
#define INTER 512
#define NEXP  16
#define TOPK  4
#define NGRP  4
#define GSZ   4
#define NE1   (NEXP + 1)

#define STG_BYTES 32768                  // 256 rows x 128B, swizzled
#define SMEM_BYTES (3 * STG_BYTES)       // 98304

#define WBIG  ((size_t)NEXP * INTER * DIM)
#define WSML  ((size_t)INTER * DIM)

// ---------------- scratch ----------------
__device__ int           g_cnt[NEXP];
__device__ int           g_tok[NEXP][T_TOK];
__device__ float         g_wt[NEXP][T_TOK];
__device__ __half        g_xrh[(size_t)T_TOK * DIM];
__device__ __half        g_acth[(size_t)NE1 * T_TOK * INTER];
__device__ __half        g_w1h[WBIG + WSML];
__device__ __half        g_w3h[WBIG + WSML];
__device__ __half        g_w2h[WBIG + WSML];

// ---------------- helpers ----------------
__device__ __forceinline__ uint32_t smem_u32(const void* p) {
    uint32_t a;
    asm("{ .reg .u64 t; cvta.to.shared.u64 t, %1; cvt.u32.u64 %0, t; }" : "=r"(a) : "l"(p));
    return a;
}
__device__ __forceinline__ void cp16(uint32_t dst, const void* src) {
    asm volatile("cp.async.ca.shared.global [%0], [%1], 16;" :: "r"(dst), "l"(src));
}
#define CP_COMMIT() asm volatile("cp.async.commit_group;")
#define CP_WAIT1()  asm volatile("cp.async.wait_group 1;")

__device__ __forceinline__ void ldsm4(uint32_t& r0, uint32_t& r1, uint32_t& r2, uint32_t& r3,
                                      uint32_t addr) {
    asm volatile("ldmatrix.sync.aligned.m8n8.x4.shared.b16 {%0,%1,%2,%3}, [%4];"
                 : "=r"(r0), "=r"(r1), "=r"(r2), "=r"(r3) : "r"(addr));
}
__device__ __forceinline__ void mma_f16(float* d, const uint32_t* a, uint32_t b0, uint32_t b1) {
    asm volatile(
        "mma.sync.aligned.m16n8k16.row.col.f32.f16.f16.f32 "
        "{%0,%1,%2,%3}, {%4,%5,%6,%7}, {%8,%9}, {%0,%1,%2,%3};"
        : "+f"(d[0]), "+f"(d[1]), "+f"(d[2]), "+f"(d[3])
        : "r"(a[0]), "r"(a[1]), "r"(a[2]), "r"(a[3]), "r"(b0), "r"(b1));
}

// ---------------- init / zero ----------------
__global__ void init_kernel() {
    int i = threadIdx.x;
    if (i < NEXP) g_cnt[i] = 0;
}
__global__ void zero_out_kernel(float* __restrict__ out) {
    size_t idx = ((size_t)blockIdx.x * blockDim.x + threadIdx.x) * 4;
    if (idx < (size_t)T_TOK * DIM)
        *(float4*)(out + idx) = make_float4(0.f, 0.f, 0.f, 0.f);
}

// ---------------- weight conversion fp32 -> fp16 ----------------
__global__ __launch_bounds__(256) void convert_w(
    const float* __restrict__ w1, const float* __restrict__ w2, const float* __restrict__ w3,
    const float* __restrict__ ws1, const float* __restrict__ ws2, const float* __restrict__ ws3)
{
    const int seg = blockIdx.y;
    const size_t n = (seg < 3) ? WBIG : WSML;
    const size_t i = ((size_t)blockIdx.x * 256 + threadIdx.x) * 8;
    if (i >= n) return;
    const float* src; __half* dst;
    switch (seg) {
        case 0: src = w1;  dst = g_w1h;        break;
        case 1: src = w3;  dst = g_w3h;        break;
        case 2: src = w2;  dst = g_w2h;        break;
        case 3: src = ws1; dst = g_w1h + WBIG; break;
        case 4: src = ws3; dst = g_w3h + WBIG; break;
        default: src = ws2; dst = g_w2h + WBIG; break;
    }
    float4 a = *(const float4*)(src + i);
    float4 b = *(const float4*)(src + i + 4);
    __half2 h0 = __floats2half2_rn(a.x, a.y), h1 = __floats2half2_rn(a.z, a.w);
    __half2 h2 = __floats2half2_rn(b.x, b.y), h3 = __floats2half2_rn(b.z, b.w);
    uint4 o;
    o.x = *(uint32_t*)&h0; o.y = *(uint32_t*)&h1;
    o.z = *(uint32_t*)&h2; o.w = *(uint32_t*)&h3;
    *(uint4*)(dst + i) = o;
}

// ---------------- gate ----------------
__global__ __launch_bounds__(256) void gate_kernel(const float* __restrict__ x,
                                                   const float* __restrict__ gw,
                                                   const float* __restrict__ gbias) {
    int t    = blockIdx.x * 8 + (threadIdx.x >> 5);
    int lane = threadIdx.x & 31;

    float xr[32];
    const float* xp = x + (size_t)t * DIM;
    __half* xo = g_xrh + (size_t)t * DIM;
#pragma unroll
    for (int i = 0; i < 32; i++) {
        xr[i] = xp[lane + i * 32];
        xo[lane + i * 32] = __float2half_rn(xr[i]);
    }

    float sc[NEXP];
#pragma unroll
    for (int e = 0; e < NEXP; e++) {
        const float* w = gw + (size_t)e * DIM;
        float acc = 0.f;
#pragma unroll
        for (int i = 0; i < 32; i++) acc += xr[i] * w[lane + i * 32];
#pragma unroll
        for (int o = 16; o > 0; o >>= 1) acc += __shfl_xor_sync(0xffffffffu, acc, o);
        sc[e] = 1.f / (1.f + expf(-acc));
    }
    if (lane == 0) {
        float s[NEXP];
#pragma unroll
        for (int e = 0; e < NEXP; e++) s[e] = sc[e] + gbias[e];
        float gm[NGRP];
#pragma unroll
        for (int g = 0; g < NGRP; g++) {
            float m = s[g * GSZ];
#pragma unroll
            for (int j = 1; j < GSZ; j++) m = fmaxf(m, s[g * GSZ + j]);
            gm[g] = m;
        }
        int g1 = 0;
#pragma unroll
        for (int g = 1; g < NGRP; g++) if (gm[g] > gm[g1]) g1 = g;
        int g2 = -1;
#pragma unroll
        for (int g = 0; g < NGRP; g++) {
            if (g == g1) continue;
            if (g2 < 0 || gm[g] > gm[g2]) g2 = g;
        }
        float sm[NEXP];
#pragma unroll
        for (int e = 0; e < NEXP; e++) {
            int g = e / GSZ;
            sm[e] = (g == g1 || g == g2) ? s[e] : -1e30f;
        }
#pragma unroll
        for (int k = 0; k < TOPK; k++) {
            int best = 0; float bv = -1e38f;
#pragma unroll
            for (int e = 0; e < NEXP; e++) if (sm[e] > bv) { bv = sm[e]; best = e; }
            sm[best] = -1e38f;
            int pos = atomicAdd(&g_cnt[best], 1);
            g_tok[best][pos] = t;
            g_wt[best][pos]  = sc[best];
        }
    }
}

// fill helper: one (row, half) = 4 cp16 chunks, swizzled dst
// dst byte = R*128 + (((h*4 + c) ^ (R&7)) << 4)
#define FILL_ROW(stageu, R, srcp) do {                                        \
        uint32_t _rb = (stageu) + (uint32_t)(R) * 128;                        \
        int _e7 = (R) & 7;                                                    \
        cp16(_rb + (uint32_t)(((h4 + 0) ^ _e7) << 4), (srcp) + 0);            \
        cp16(_rb + (uint32_t)(((h4 + 1) ^ _e7) << 4), (srcp) + 8);            \
        cp16(_rb + (uint32_t)(((h4 + 2) ^ _e7) << 4), (srcp) + 16);           \
        cp16(_rb + (uint32_t)(((h4 + 3) ^ _e7) << 4), (srcp) + 24);           \
    } while (0)

// =====================================================================
// stage A: act = silu(X@W1^T)*(X@W3^T) — 128 thr, 4 warps (2x2), 64x64 warp tiles
// block tile M=128, N=64 (of each W1/W3), BK=64, 3-stage cp.async, swizzled smem
// stage layout rows: A 0-127 | W1 128-191 | W3 192-255
// =====================================================================
__global__ __launch_bounds__(128, 2) void ffn_in_mma()
{
    const int e   = blockIdx.z;
    const int cnt = (e == NEXP) ? T_TOK : g_cnt[e];
    const int m0  = blockIdx.x * 128;
    if (m0 >= cnt) return;
    const int n0  = blockIdx.y * 64;

    extern __shared__ char smc[];
    const uint32_t sb = smem_u32(smc);
    const int tid = threadIdx.x;

    // fill assignments: 4 passes x (row, half); half h = tid&1, base row = tid>>1
    const int fr = tid >> 1, h4 = (tid & 1) * 4;
    const int hoff = (tid & 1) * 32;    // halfs
    int ai0 = m0 + fr;       if (ai0 > cnt - 1) ai0 = cnt - 1;
    int ai1 = m0 + fr + 64;  if (ai1 > cnt - 1) ai1 = cnt - 1;
    const int tok0 = (e == NEXP) ? (m0 + fr)      : g_tok[e][ai0];
    const int tok1 = (e == NEXP) ? (m0 + fr + 64) : g_tok[e][ai1];
    const __half* s0 = g_xrh + (size_t)tok0 * DIM + hoff;
    const __half* s1 = g_xrh + (size_t)tok1 * DIM + hoff;
    const __half* s2 = g_w1h + (size_t)e * INTER * DIM + (size_t)(n0 + fr) * DIM + hoff;
    const __half* s3 = g_w3h + (size_t)e * INTER * DIM + (size_t)(n0 + fr) * DIM + hoff;

    const int lane = tid & 31, warp = tid >> 5;
    const int wm = warp >> 1, wn = warp & 1;
    const int gid = lane >> 2, tig = lane & 3;

    const uint32_t aRowB = (uint32_t)(lane & 15) * 128;
    const uint32_t ahi   = (uint32_t)(lane >> 4) * 16;
    const uint32_t bRowB = ((uint32_t)(lane & 7) + (uint32_t)((lane >> 4) & 1) * 8) * 128;
    const uint32_t bhi   = (uint32_t)((lane >> 3) & 1) * 16;
    const uint32_t sw    = (uint32_t)(lane & 7) * 16;

    float acc1[4][4][4], acc3[4][4][4];
#pragma unroll
    for (int i = 0; i < 4; i++)
#pragma unroll
        for (int j = 0; j < 4; j++)
#pragma unroll
            for (int k = 0; k < 4; k++) { acc1[i][j][k] = 0.f; acc3[i][j][k] = 0.f; }

#define ISSUE_A(kk) do {                                        \
        uint32_t _st = sb + (uint32_t)(((kk) % 3) * STG_BYTES); \
        const int _ko = (kk) * 64;                              \
        FILL_ROW(_st, fr,        s0 + _ko);                     \
        FILL_ROW(_st, fr + 64,   s1 + _ko);                     \
        FILL_ROW(_st, fr + 128,  s2 + _ko);                     \
        FILL_ROW(_st, fr + 192,  s3 + _ko);                     \
        CP_COMMIT();                                            \
    } while (0)

    ISSUE_A(0);
    ISSUE_A(1);

    const int KITER = DIM / 64;
    for (int kk = 0; kk < KITER; kk++) {
        CP_WAIT1();
        __syncthreads();
        if (kk + 2 < KITER) { ISSUE_A(kk + 2); } else { CP_COMMIT(); }

        const uint32_t stage = sb + (uint32_t)((kk % 3) * STG_BYTES);
        const uint32_t Ab  = stage + (uint32_t)(wm * 64) * 128 + aRowB;
        const uint32_t B1b = stage + 16384u + (uint32_t)(wn * 32) * 128 + bRowB;
        const uint32_t B3b = stage + 24576u + (uint32_t)(wn * 32) * 128 + bRowB;

#pragma unroll
        for (int ks = 0; ks < 4; ks++) {
            const uint32_t akx = ((uint32_t)(ks * 32) + ahi) ^ sw;
            const uint32_t bkx = ((uint32_t)(ks * 32) + bhi) ^ sw;
            uint32_t af[4][4];
#pragma unroll
            for (int mt = 0; mt < 4; mt++)
                ldsm4(af[mt][0], af[mt][1], af[mt][2], af[mt][3],
                      Ab + (uint32_t)(mt * 16) * 128 + akx);
            uint32_t b1[2][4], b3[2][4];
#pragma unroll
            for (int ntp = 0; ntp < 2; ntp++)
                ldsm4(b1[ntp][0], b1[ntp][1], b1[ntp][2], b1[ntp][3],
                      B1b + (uint32_t)(ntp * 16) * 128 + bkx);
#pragma unroll
            for (int ntp = 0; ntp < 2; ntp++)
                ldsm4(b3[ntp][0], b3[ntp][1], b3[ntp][2], b3[ntp][3],
                      B3b + (uint32_t)(ntp * 16) * 128 + bkx);
#pragma unroll
            for (int ntp = 0; ntp < 2; ntp++)
#pragma unroll
                for (int mt = 0; mt < 4; mt++) {
                    mma_f16(acc1[mt][2 * ntp + 0], af[mt], b1[ntp][0], b1[ntp][1]);
                    mma_f16(acc1[mt][2 * ntp + 1], af[mt], b1[ntp][2], b1[ntp][3]);
                    mma_f16(acc3[mt][2 * ntp + 0], af[mt], b3[ntp][0], b3[ntp][1]);
                    mma_f16(acc3[mt][2 * ntp + 1], af[mt], b3[ntp][2], b3[ntp][3]);
                }
        }
    }

    // epilogue: act = silu(h1)*h3 -> fp16
#pragma unroll
    for (int mt = 0; mt < 4; mt++) {
#pragma unroll
        for (int h = 0; h < 2; h++) {
            const int m = m0 + wm * 64 + mt * 16 + gid + h * 8;
            if (m >= cnt) continue;
            __half* dst = &g_acth[((size_t)e * T_TOK + m) * INTER + n0 + wn * 32];
#pragma unroll
            for (int nt = 0; nt < 4; nt++) {
                float v0 = acc1[mt][nt][h * 2 + 0], u0 = acc3[mt][nt][h * 2 + 0];
                float v1 = acc1[mt][nt][h * 2 + 1], u1 = acc3[mt][nt][h * 2 + 1];
                *(__half2*)(dst + nt * 8 + tig * 2) =
                    __floats2half2_rn((v0 / (1.f + __expf(-v0))) * u0,
                                      (v1 / (1.f + __expf(-v1))) * u1);
            }
        }
    }
#undef ISSUE_A
}

// =====================================================================
// stage B: out += (act @ W2^T) * weight — 128 thr, 4 warps (2x2), 64x64 warp tiles
// block tile M=128, N=128, BK=64; atomic combine into out
// stage layout rows: A 0-127 | W2 128-255
// =====================================================================
__global__ __launch_bounds__(128, 2) void ffn_out_mma(float* __restrict__ out)
{
    const int e   = blockIdx.z;
    const int cnt = (e == NEXP) ? T_TOK : g_cnt[e];
    const int m0  = blockIdx.x * 128;
    if (m0 >= cnt) return;
    const int n0  = blockIdx.y * 128;

    extern __shared__ char smc[];
    const uint32_t sb = smem_u32(smc);
    const int tid = threadIdx.x;

    const int fr = tid >> 1, h4 = (tid & 1) * 4;
    const int hoff = (tid & 1) * 32;
    int ai0 = m0 + fr;      if (ai0 > cnt - 1) ai0 = cnt - 1;
    int ai1 = m0 + fr + 64; if (ai1 > cnt - 1) ai1 = cnt - 1;
    const __half* s0 = g_acth + ((size_t)e * T_TOK + ai0) * INTER + hoff;
    const __half* s1 = g_acth + ((size_t)e * T_TOK + ai1) * INTER + hoff;
    const __half* s2 = g_w2h + (size_t)e * DIM * INTER + (size_t)(n0 + fr) * INTER + hoff;
    const __half* s3 = s2 + (size_t)64 * INTER;

    const int lane = tid & 31, warp = tid >> 5;
    const int wm = warp >> 1, wn = warp & 1;
    const int gid = lane >> 2, tig = lane & 3;

    const uint32_t aRowB = (uint32_t)(lane & 15) * 128;
    const uint32_t ahi   = (uint32_t)(lane >> 4) * 16;
    const uint32_t bRowB = ((uint32_t)(lane & 7) + (uint32_t)((lane >> 4) & 1) * 8) * 128;
    const uint32_t bhi   = (uint32_t)((lane >> 3) & 1) * 16;
    const uint32_t sw    = (uint32_t)(lane & 7) * 16;

    float acc[4][8][4];
#pragma unroll
    for (int i = 0; i < 4; i++)
#pragma unroll
        for (int j = 0; j < 8; j++)
#pragma unroll
            for (int k = 0; k < 4; k++) acc[i][j][k] = 0.f;

#define ISSUE_B(kk) do {                                        \
        uint32_t _st = sb + (uint32_t)(((kk) % 3) * STG_BYTES); \
        const int _ko = (kk) * 64;                              \
        FILL_ROW(_st, fr,        s0 + _ko);                     \
        FILL_ROW(_st, fr + 64,   s1 + _ko);                     \
        FILL_ROW(_st, fr + 128,  s2 + _ko);                     \
        FILL_ROW(_st, fr + 192,  s3 + _ko);                     \
        CP_COMMIT();                                            \
    } while (0)

    ISSUE_B(0);
    ISSUE_B(1);

    const int KITER = INTER / 64;
    for (int kk = 0; kk < KITER; kk++) {
        CP_WAIT1();
        __syncthreads();
        if (kk + 2 < KITER) { ISSUE_B(kk + 2); } else { CP_COMMIT(); }

        const uint32_t stage = sb + (uint32_t)((kk % 3) * STG_BYTES);
        const uint32_t Ab = stage + (uint32_t)(wm * 64) * 128 + aRowB;
        const uint32_t Bb = stage + 16384u + (uint32_t)(wn * 64) * 128 + bRowB;

#pragma unroll
        for (int ks = 0; ks < 4; ks++) {
            const uint32_t akx = ((uint32_t)(ks * 32) + ahi) ^ sw;
            const uint32_t bkx = ((uint32_t)(ks * 32) + bhi) ^ sw;
            uint32_t af[4][4];
#pragma unroll
            for (int mt = 0; mt < 4; mt++)
                ldsm4(af[mt][0], af[mt][1], af[mt][2], af[mt][3],
                      Ab + (uint32_t)(mt * 16) * 128 + akx);
            uint32_t bf[4][4];
#pragma unroll
            for (int ntp = 0; ntp < 4; ntp++)
                ldsm4(bf[ntp][0], bf[ntp][1], bf[ntp][2], bf[ntp][3],
                      Bb + (uint32_t)(ntp * 16) * 128 + bkx);
#pragma unroll
            for (int ntp = 0; ntp < 4; ntp++)
#pragma unroll
                for (int mt = 0; mt < 4; mt++) {
                    mma_f16(acc[mt][2 * ntp + 0], af[mt], bf[ntp][0], bf[ntp][1]);
                    mma_f16(acc[mt][2 * ntp + 1], af[mt], bf[ntp][2], bf[ntp][3]);
                }
        }
    }

    // epilogue: atomic combine into out
#pragma unroll
    for (int mt = 0; mt < 4; mt++) {
#pragma unroll
        for (int h = 0; h < 2; h++) {
            const int m = m0 + wm * 64 + mt * 16 + gid + h * 8;
            if (m >= cnt) continue;
            float wt;
            int tokm;
            if (e == NEXP) { tokm = m; wt = 1.f; }
            else           { tokm = g_tok[e][m]; wt = g_wt[e][m]; }
            float* dst = out + (size_t)tokm * DIM + n0 + wn * 64;
#pragma unroll
            for (int nt = 0; nt < 8; nt++) {
                atomicAdd(dst + nt * 8 + tig * 2 + 0, acc[mt][nt][h * 2 + 0] * wt);
                atomicAdd(dst + nt * 8 + tig * 2 + 1, acc[mt][nt][h * 2 + 1] * wt);
            }
        }
    }
#undef ISSUE_B
}

// ---------------- launch ----------------
extern "C" void kernel_launch(void* const* d_in, const int* in_sizes, int n_in,
                              void* d_out, int out_size) {
    const float* x   = (const float*)d_in[0];
    const float* gw  = (const float*)d_in[1];
    const float* gb  = (const float*)d_in[2];
    const float* w1  = (const float*)d_in[3];
    const float* w2  = (const float*)d_in[4];
    const float* w3  = (const float*)d_in[5];
    const float* ws1 = (const float*)d_in[6];
    const float* ws2 = (const float*)d_in[7];
    const float* ws3 = (const float*)d_in[8];
    float* out = (float*)d_out;

    cudaFuncSetAttribute(ffn_in_mma,  cudaFuncAttributeMaxDynamicSharedMemorySize, SMEM_BYTES);
    cudaFuncSetAttribute(ffn_out_mma, cudaFuncAttributeMaxDynamicSharedMemorySize, SMEM_BYTES);

    init_kernel<<<1, 32>>>();
    zero_out_kernel<<<(T_TOK * DIM / 4 + 255) / 256, 256>>>(out);
    convert_w<<<dim3(4096, 6), 256>>>(w1, w2, w3, ws1, ws2, ws3);
    gate_kernel<<<T_TOK / 8, 256>>>(x, gw, gb);
    ffn_in_mma<<<dim3(T_TOK / 128, INTER / 64, NE1), 128, SMEM_BYTES>>>();
    ffn_out_mma<<<dim3(T_TOK / 128, DIM / 128, NE1), 128, SMEM_BYTES>>>(out);
}

// round 8
// speedup vs baseline: 4.2730x; 1.0183x over previous
#include <cuda_runtime.h>
#include <cuda_fp16.h>
#include <math.h>
#include <stdint.h>

#define T_TOK 2048
#define DIM   1024
#define INTER 512
#define NEXP  16
#define TOPK  4
#define NGRP  4
#define GSZ   4
#define NE1   (NEXP + 1)

#define STG_BYTES 32768                  // 256 rows x 128B, swizzled
#define SMEM_BYTES (3 * STG_BYTES)       // 98304

#define WBIG  ((size_t)NEXP * INTER * DIM)
#define WSML  ((size_t)INTER * DIM)

// ---------------- scratch ----------------
__device__ int           g_cnt[NEXP];
__device__ int           g_tok[NEXP][T_TOK];
__device__ unsigned char g_slot[NEXP][T_TOK];
__device__ float         g_wt[NEXP][T_TOK];
__device__ __half        g_xrh[(size_t)T_TOK * DIM];
__device__ __half        g_acth[(size_t)NE1 * T_TOK * INTER];
__device__ float         g_ybuf[TOPK][(size_t)T_TOK * DIM];
__device__ __half        g_w1h[WBIG + WSML];
__device__ __half        g_w3h[WBIG + WSML];
__device__ __half        g_w2h[WBIG + WSML];

// ---------------- helpers ----------------
__device__ __forceinline__ uint32_t smem_u32(const void* p) {
    uint32_t a;
    asm("{ .reg .u64 t; cvta.to.shared.u64 t, %1; cvt.u32.u64 %0, t; }" : "=r"(a) : "l"(p));
    return a;
}
__device__ __forceinline__ void cp16(uint32_t dst, const void* src) {
    asm volatile("cp.async.ca.shared.global [%0], [%1], 16;" :: "r"(dst), "l"(src));
}
#define CP_COMMIT() asm volatile("cp.async.commit_group;")
#define CP_WAIT1()  asm volatile("cp.async.wait_group 1;")

__device__ __forceinline__ void ldsm4(uint32_t& r0, uint32_t& r1, uint32_t& r2, uint32_t& r3,
                                      uint32_t addr) {
    asm volatile("ldmatrix.sync.aligned.m8n8.x4.shared.b16 {%0,%1,%2,%3}, [%4];"
                 : "=r"(r0), "=r"(r1), "=r"(r2), "=r"(r3) : "r"(addr));
}
__device__ __forceinline__ void mma_f16(float* d, const uint32_t* a, uint32_t b0, uint32_t b1) {
    asm volatile(
        "mma.sync.aligned.m16n8k16.row.col.f32.f16.f16.f32 "
        "{%0,%1,%2,%3}, {%4,%5,%6,%7}, {%8,%9}, {%0,%1,%2,%3};"
        : "+f"(d[0]), "+f"(d[1]), "+f"(d[2]), "+f"(d[3])
        : "r"(a[0]), "r"(a[1]), "r"(a[2]), "r"(a[3]), "r"(b0), "r"(b1));
}

// ---------------- weight conversion fp32 -> fp16 (also zeroes g_cnt) ----------------
__global__ __launch_bounds__(256) void convert_w(
    const float* __restrict__ w1, const float* __restrict__ w2, const float* __restrict__ w3,
    const float* __restrict__ ws1, const float* __restrict__ ws2, const float* __restrict__ ws3)
{
    if (blockIdx.x == 0 && blockIdx.y == 0 && threadIdx.x < NEXP)
        g_cnt[threadIdx.x] = 0;
    const int seg = blockIdx.y;
    const size_t n = (seg < 3) ? WBIG : WSML;
    const size_t i = ((size_t)blockIdx.x * 256 + threadIdx.x) * 8;
    if (i >= n) return;
    const float* src; __half* dst;
    switch (seg) {
        case 0: src = w1;  dst = g_w1h;        break;
        case 1: src = w3;  dst = g_w3h;        break;
        case 2: src = w2;  dst = g_w2h;        break;
        case 3: src = ws1; dst = g_w1h + WBIG; break;
        case 4: src = ws3; dst = g_w3h + WBIG; break;
        default: src = ws2; dst = g_w2h + WBIG; break;
    }
    float4 a = *(const float4*)(src + i);
    float4 b = *(const float4*)(src + i + 4);
    __half2 h0 = __floats2half2_rn(a.x, a.y), h1 = __floats2half2_rn(a.z, a.w);
    __half2 h2 = __floats2half2_rn(b.x, b.y), h3 = __floats2half2_rn(b.z, b.w);
    uint4 o;
    o.x = *(uint32_t*)&h0; o.y = *(uint32_t*)&h1;
    o.z = *(uint32_t*)&h2; o.w = *(uint32_t*)&h3;
    *(uint4*)(dst + i) = o;
}

// ---------------- gate: vectorized; 1 warp/token, 8 warps/block ----------------
__global__ __launch_bounds__(256) void gate_kernel(const float* __restrict__ x,
                                                   const float* __restrict__ gw,
                                                   const float* __restrict__ gbias) {
    int t    = blockIdx.x * 8 + (threadIdx.x >> 5);
    int lane = threadIdx.x & 31;

    // lane owns dims {4*lane + 128*i + 0..3}, i = 0..7
    float4 xr[8];
    const float4* xp = (const float4*)(x + (size_t)t * DIM) + lane;
#pragma unroll
    for (int i = 0; i < 8; i++) xr[i] = xp[i * 32];

    // fp16 copy of x
    __half* xo = g_xrh + (size_t)t * DIM + lane * 4;
#pragma unroll
    for (int i = 0; i < 8; i++) {
        __half2 lo = __floats2half2_rn(xr[i].x, xr[i].y);
        __half2 hi = __floats2half2_rn(xr[i].z, xr[i].w);
        uint2 u;
        u.x = *(uint32_t*)&lo; u.y = *(uint32_t*)&hi;
        *(uint2*)(xo + i * 128) = u;
    }

    float sc[NEXP];
#pragma unroll
    for (int e = 0; e < NEXP; e++) {
        const float4* w = (const float4*)(gw + (size_t)e * DIM) + lane;
        float acc = 0.f;
#pragma unroll
        for (int i = 0; i < 8; i++) {
            float4 wv = w[i * 32];
            acc += xr[i].x * wv.x + xr[i].y * wv.y + xr[i].z * wv.z + xr[i].w * wv.w;
        }
#pragma unroll
        for (int o = 16; o > 0; o >>= 1) acc += __shfl_xor_sync(0xffffffffu, acc, o);
        sc[e] = 1.f / (1.f + __expf(-acc));
    }
    if (lane == 0) {
        float s[NEXP];
#pragma unroll
        for (int e = 0; e < NEXP; e++) s[e] = sc[e] + gbias[e];
        float gm[NGRP];
#pragma unroll
        for (int g = 0; g < NGRP; g++) {
            float m = s[g * GSZ];
#pragma unroll
            for (int j = 1; j < GSZ; j++) m = fmaxf(m, s[g * GSZ + j]);
            gm[g] = m;
        }
        int g1 = 0;
#pragma unroll
        for (int g = 1; g < NGRP; g++) if (gm[g] > gm[g1]) g1 = g;
        int g2 = -1;
#pragma unroll
        for (int g = 0; g < NGRP; g++) {
            if (g == g1) continue;
            if (g2 < 0 || gm[g] > gm[g2]) g2 = g;
        }
        float sm[NEXP];
#pragma unroll
        for (int e = 0; e < NEXP; e++) {
            int g = e / GSZ;
            sm[e] = (g == g1 || g == g2) ? s[e] : -1e30f;
        }
#pragma unroll
        for (int k = 0; k < TOPK; k++) {
            int best = 0; float bv = -1e38f;
#pragma unroll
            for (int e = 0; e < NEXP; e++) if (sm[e] > bv) { bv = sm[e]; best = e; }
            sm[best] = -1e38f;
            int pos = atomicAdd(&g_cnt[best], 1);
            g_tok[best][pos]  = t;
            g_slot[best][pos] = (unsigned char)k;
            g_wt[best][pos]   = sc[best];
        }
    }
}

// fill helper: one (row, half) = 4 cp16 chunks, swizzled dst
#define FILL_ROW(stageu, R, srcp) do {                                        \
        uint32_t _rb = (stageu) + (uint32_t)(R) * 128;                        \
        int _e7 = (R) & 7;                                                    \
        cp16(_rb + (uint32_t)(((h4 + 0) ^ _e7) << 4), (srcp) + 0);            \
        cp16(_rb + (uint32_t)(((h4 + 1) ^ _e7) << 4), (srcp) + 8);            \
        cp16(_rb + (uint32_t)(((h4 + 2) ^ _e7) << 4), (srcp) + 16);           \
        cp16(_rb + (uint32_t)(((h4 + 3) ^ _e7) << 4), (srcp) + 24);           \
    } while (0)

// =====================================================================
// stage A: act = silu(X@W1^T)*(X@W3^T) — 128 thr, 4 warps (2x2), 64x64 warp tiles
// =====================================================================
__global__ __launch_bounds__(128, 2) void ffn_in_mma()
{
    const int e   = blockIdx.z;
    const int cnt = (e == NEXP) ? T_TOK : g_cnt[e];
    const int m0  = blockIdx.x * 128;
    if (m0 >= cnt) return;
    const int n0  = blockIdx.y * 64;

    extern __shared__ char smc[];
    const uint32_t sb = smem_u32(smc);
    const int tid = threadIdx.x;

    const int fr = tid >> 1, h4 = (tid & 1) * 4;
    const int hoff = (tid & 1) * 32;
    int ai0 = m0 + fr;       if (ai0 > cnt - 1) ai0 = cnt - 1;
    int ai1 = m0 + fr + 64;  if (ai1 > cnt - 1) ai1 = cnt - 1;
    const int tok0 = (e == NEXP) ? (m0 + fr)      : g_tok[e][ai0];
    const int tok1 = (e == NEXP) ? (m0 + fr + 64) : g_tok[e][ai1];
    const __half* s0 = g_xrh + (size_t)tok0 * DIM + hoff;
    const __half* s1 = g_xrh + (size_t)tok1 * DIM + hoff;
    const __half* s2 = g_w1h + (size_t)e * INTER * DIM + (size_t)(n0 + fr) * DIM + hoff;
    const __half* s3 = g_w3h + (size_t)e * INTER * DIM + (size_t)(n0 + fr) * DIM + hoff;

    const int lane = tid & 31, warp = tid >> 5;
    const int wm = warp >> 1, wn = warp & 1;
    const int gid = lane >> 2, tig = lane & 3;

    const uint32_t aRowB = (uint32_t)(lane & 15) * 128;
    const uint32_t ahi   = (uint32_t)(lane >> 4) * 16;
    const uint32_t bRowB = ((uint32_t)(lane & 7) + (uint32_t)((lane >> 4) & 1) * 8) * 128;
    const uint32_t bhi   = (uint32_t)((lane >> 3) & 1) * 16;
    const uint32_t sw    = (uint32_t)(lane & 7) * 16;

    float acc1[4][4][4], acc3[4][4][4];
#pragma unroll
    for (int i = 0; i < 4; i++)
#pragma unroll
        for (int j = 0; j < 4; j++)
#pragma unroll
            for (int k = 0; k < 4; k++) { acc1[i][j][k] = 0.f; acc3[i][j][k] = 0.f; }

#define ISSUE_A(kk) do {                                        \
        uint32_t _st = sb + (uint32_t)(((kk) % 3) * STG_BYTES); \
        const int _ko = (kk) * 64;                              \
        FILL_ROW(_st, fr,        s0 + _ko);                     \
        FILL_ROW(_st, fr + 64,   s1 + _ko);                     \
        FILL_ROW(_st, fr + 128,  s2 + _ko);                     \
        FILL_ROW(_st, fr + 192,  s3 + _ko);                     \
        CP_COMMIT();                                            \
    } while (0)

    ISSUE_A(0);
    ISSUE_A(1);

    const int KITER = DIM / 64;
    for (int kk = 0; kk < KITER; kk++) {
        CP_WAIT1();
        __syncthreads();
        if (kk + 2 < KITER) { ISSUE_A(kk + 2); } else { CP_COMMIT(); }

        const uint32_t stage = sb + (uint32_t)((kk % 3) * STG_BYTES);
        const uint32_t Ab  = stage + (uint32_t)(wm * 64) * 128 + aRowB;
        const uint32_t B1b = stage + 16384u + (uint32_t)(wn * 32) * 128 + bRowB;
        const uint32_t B3b = stage + 24576u + (uint32_t)(wn * 32) * 128 + bRowB;

#pragma unroll
        for (int ks = 0; ks < 4; ks++) {
            const uint32_t akx = ((uint32_t)(ks * 32) + ahi) ^ sw;
            const uint32_t bkx = ((uint32_t)(ks * 32) + bhi) ^ sw;
            uint32_t af[4][4];
#pragma unroll
            for (int mt = 0; mt < 4; mt++)
                ldsm4(af[mt][0], af[mt][1], af[mt][2], af[mt][3],
                      Ab + (uint32_t)(mt * 16) * 128 + akx);
            uint32_t b1[2][4], b3[2][4];
#pragma unroll
            for (int ntp = 0; ntp < 2; ntp++)
                ldsm4(b1[ntp][0], b1[ntp][1], b1[ntp][2], b1[ntp][3],
                      B1b + (uint32_t)(ntp * 16) * 128 + bkx);
#pragma unroll
            for (int ntp = 0; ntp < 2; ntp++)
                ldsm4(b3[ntp][0], b3[ntp][1], b3[ntp][2], b3[ntp][3],
                      B3b + (uint32_t)(ntp * 16) * 128 + bkx);
#pragma unroll
            for (int ntp = 0; ntp < 2; ntp++)
#pragma unroll
                for (int mt = 0; mt < 4; mt++) {
                    mma_f16(acc1[mt][2 * ntp + 0], af[mt], b1[ntp][0], b1[ntp][1]);
                    mma_f16(acc1[mt][2 * ntp + 1], af[mt], b1[ntp][2], b1[ntp][3]);
                    mma_f16(acc3[mt][2 * ntp + 0], af[mt], b3[ntp][0], b3[ntp][1]);
                    mma_f16(acc3[mt][2 * ntp + 1], af[mt], b3[ntp][2], b3[ntp][3]);
                }
        }
    }

    // epilogue: act = silu(h1)*h3 -> fp16
#pragma unroll
    for (int mt = 0; mt < 4; mt++) {
#pragma unroll
        for (int h = 0; h < 2; h++) {
            const int m = m0 + wm * 64 + mt * 16 + gid + h * 8;
            if (m >= cnt) continue;
            __half* dst = &g_acth[((size_t)e * T_TOK + m) * INTER + n0 + wn * 32];
#pragma unroll
            for (int nt = 0; nt < 4; nt++) {
                float v0 = acc1[mt][nt][h * 2 + 0], u0 = acc3[mt][nt][h * 2 + 0];
                float v1 = acc1[mt][nt][h * 2 + 1], u1 = acc3[mt][nt][h * 2 + 1];
                *(__half2*)(dst + nt * 8 + tig * 2) =
                    __floats2half2_rn((v0 / (1.f + __expf(-v0))) * u0,
                                      (v1 / (1.f + __expf(-v1))) * u1);
            }
        }
    }
#undef ISSUE_A
}

// =====================================================================
// stage B: y = (act @ W2^T) — shared -> out direct, routed -> ybuf slot
// =====================================================================
__global__ __launch_bounds__(128, 2) void ffn_out_mma(float* __restrict__ out)
{
    const int e   = blockIdx.z;
    const int cnt = (e == NEXP) ? T_TOK : g_cnt[e];
    const int m0  = blockIdx.x * 128;
    if (m0 >= cnt) return;
    const int n0  = blockIdx.y * 128;

    extern __shared__ char smc[];
    const uint32_t sb = smem_u32(smc);
    const int tid = threadIdx.x;

    const int fr = tid >> 1, h4 = (tid & 1) * 4;
    const int hoff = (tid & 1) * 32;
    int ai0 = m0 + fr;      if (ai0 > cnt - 1) ai0 = cnt - 1;
    int ai1 = m0 + fr + 64; if (ai1 > cnt - 1) ai1 = cnt - 1;
    const __half* s0 = g_acth + ((size_t)e * T_TOK + ai0) * INTER + hoff;
    const __half* s1 = g_acth + ((size_t)e * T_TOK + ai1) * INTER + hoff;
    const __half* s2 = g_w2h + (size_t)e * DIM * INTER + (size_t)(n0 + fr) * INTER + hoff;
    const __half* s3 = s2 + (size_t)64 * INTER;

    const int lane = tid & 31, warp = tid >> 5;
    const int wm = warp >> 1, wn = warp & 1;
    const int gid = lane >> 2, tig = lane & 3;

    const uint32_t aRowB = (uint32_t)(lane & 15) * 128;
    const uint32_t ahi   = (uint32_t)(lane >> 4) * 16;
    const uint32_t bRowB = ((uint32_t)(lane & 7) + (uint32_t)((lane >> 4) & 1) * 8) * 128;
    const uint32_t bhi   = (uint32_t)((lane >> 3) & 1) * 16;
    const uint32_t sw    = (uint32_t)(lane & 7) * 16;

    float acc[4][8][4];
#pragma unroll
    for (int i = 0; i < 4; i++)
#pragma unroll
        for (int j = 0; j < 8; j++)
#pragma unroll
            for (int k = 0; k < 4; k++) acc[i][j][k] = 0.f;

#define ISSUE_B(kk) do {                                        \
        uint32_t _st = sb + (uint32_t)(((kk) % 3) * STG_BYTES); \
        const int _ko = (kk) * 64;                              \
        FILL_ROW(_st, fr,        s0 + _ko);                     \
        FILL_ROW(_st, fr + 64,   s1 + _ko);                     \
        FILL_ROW(_st, fr + 128,  s2 + _ko);                     \
        FILL_ROW(_st, fr + 192,  s3 + _ko);                     \
        CP_COMMIT();                                            \
    } while (0)

    ISSUE_B(0);
    ISSUE_B(1);

    const int KITER = INTER / 64;
    for (int kk = 0; kk < KITER; kk++) {
        CP_WAIT1();
        __syncthreads();
        if (kk + 2 < KITER) { ISSUE_B(kk + 2); } else { CP_COMMIT(); }

        const uint32_t stage = sb + (uint32_t)((kk % 3) * STG_BYTES);
        const uint32_t Ab = stage + (uint32_t)(wm * 64) * 128 + aRowB;
        const uint32_t Bb = stage + 16384u + (uint32_t)(wn * 64) * 128 + bRowB;

#pragma unroll
        for (int ks = 0; ks < 4; ks++) {
            const uint32_t akx = ((uint32_t)(ks * 32) + ahi) ^ sw;
            const uint32_t bkx = ((uint32_t)(ks * 32) + bhi) ^ sw;
            uint32_t af[4][4];
#pragma unroll
            for (int mt = 0; mt < 4; mt++)
                ldsm4(af[mt][0], af[mt][1], af[mt][2], af[mt][3],
                      Ab + (uint32_t)(mt * 16) * 128 + akx);
            uint32_t bf[4][4];
#pragma unroll
            for (int ntp = 0; ntp < 4; ntp++)
                ldsm4(bf[ntp][0], bf[ntp][1], bf[ntp][2], bf[ntp][3],
                      Bb + (uint32_t)(ntp * 16) * 128 + bkx);
#pragma unroll
            for (int ntp = 0; ntp < 4; ntp++)
#pragma unroll
                for (int mt = 0; mt < 4; mt++) {
                    mma_f16(acc[mt][2 * ntp + 0], af[mt], bf[ntp][0], bf[ntp][1]);
                    mma_f16(acc[mt][2 * ntp + 1], af[mt], bf[ntp][2], bf[ntp][3]);
                }
        }
    }

    // epilogue: shared expert -> out; routed -> ybuf[slot]
#pragma unroll
    for (int mt = 0; mt < 4; mt++) {
#pragma unroll
        for (int h = 0; h < 2; h++) {
            const int m = m0 + wm * 64 + mt * 16 + gid + h * 8;
            if (m >= cnt) continue;
            float wt = 1.f;
            float* dst;
            if (e == NEXP) {
                dst = out + (size_t)m * DIM + n0 + wn * 64;
            } else {
                const int tokm = g_tok[e][m];
                const int sl   = g_slot[e][m];
                wt             = g_wt[e][m];
                dst = &g_ybuf[sl][(size_t)tokm * DIM + n0 + wn * 64];
            }
#pragma unroll
            for (int nt = 0; nt < 8; nt++) {
                *(float2*)(dst + nt * 8 + tig * 2) =
                    make_float2(acc[mt][nt][h * 2 + 0] * wt,
                                acc[mt][nt][h * 2 + 1] * wt);
            }
        }
    }
#undef ISSUE_B
}

// ---------------- reduce: out += sum_k ybuf[k] ----------------
__global__ void reduce_kernel(float* __restrict__ out) {
    size_t idx = ((size_t)blockIdx.x * blockDim.x + threadIdx.x) * 4;
    if (idx < (size_t)T_TOK * DIM) {
        float4 o = *(float4*)(out + idx);
        float4 a = *(const float4*)(&g_ybuf[0][idx]);
        float4 b = *(const float4*)(&g_ybuf[1][idx]);
        float4 c = *(const float4*)(&g_ybuf[2][idx]);
        float4 d = *(const float4*)(&g_ybuf[3][idx]);
        o.x += a.x + b.x + c.x + d.x;
        o.y += a.y + b.y + c.y + d.y;
        o.z += a.z + b.z + c.z + d.z;
        o.w += a.w + b.w + c.w + d.w;
        *(float4*)(out + idx) = o;
    }
}

// ---------------- launch ----------------
extern "C" void kernel_launch(void* const* d_in, const int* in_sizes, int n_in,
                              void* d_out, int out_size) {
    const float* x   = (const float*)d_in[0];
    const float* gw  = (const float*)d_in[1];
    const float* gb  = (const float*)d_in[2];
    const float* w1  = (const float*)d_in[3];
    const float* w2  = (const float*)d_in[4];
    const float* w3  = (const float*)d_in[5];
    const float* ws1 = (const float*)d_in[6];
    const float* ws2 = (const float*)d_in[7];
    const float* ws3 = (const float*)d_in[8];
    float* out = (float*)d_out;

    cudaFuncSetAttribute(ffn_in_mma,  cudaFuncAttributeMaxDynamicSharedMemorySize, SMEM_BYTES);
    cudaFuncSetAttribute(ffn_out_mma, cudaFuncAttributeMaxDynamicSharedMemorySize, SMEM_BYTES);

    convert_w<<<dim3(4096, 6), 256>>>(w1, w2, w3, ws1, ws2, ws3);
    gate_kernel<<<T_TOK / 8, 256>>>(x, gw, gb);
    ffn_in_mma<<<dim3(T_TOK / 128, INTER / 64, NE1), 128, SMEM_BYTES>>>();
    ffn_out_mma<<<dim3(T_TOK / 128, DIM / 128, NE1), 128, SMEM_BYTES>>>(out);
    reduce_kernel<<<(T_TOK * DIM / 4 + 255) / 256, 256>>>(out);
}

// round 9
// speedup vs baseline: 4.3101x; 1.0087x over previous
#include <cuda_runtime.h>
#include <cuda_fp16.h>
#include <math.h>
#include <stdint.h>

#define T_TOK 2048
#define DIM   1024
#define INTER 512
#define NEXP  16
#define TOPK  4
#define NGRP  4
#define GSZ   4
#define NE1   (NEXP + 1)

#define STG_BYTES 32768
#define SMEM_BYTES (3 * STG_BYTES)

#define WBIG  ((size_t)NEXP * INTER * DIM)
#define WSML  ((size_t)INTER * DIM)

// ---------------- scratch ----------------
__device__ int           g_cnt[NEXP];
__device__ int           g_tok[NEXP][T_TOK];
__device__ unsigned char g_slot[NEXP][T_TOK];
__device__ float         g_wt[NEXP][T_TOK];
__device__ __half        g_xrh[(size_t)T_TOK * DIM];
__device__ __half        g_acth[(size_t)NE1 * T_TOK * INTER];
__device__ float         g_ybuf[TOPK][(size_t)T_TOK * DIM];
__device__ __half        g_w1h[WBIG + WSML];
__device__ __half        g_w3h[WBIG + WSML];
__device__ __half        g_w2h[WBIG + WSML];

// ---------------- helpers ----------------
__device__ __forceinline__ uint32_t smem_u32(const void* p) {
    uint32_t a;
    asm("{ .reg .u64 t; cvta.to.shared.u64 t, %1; cvt.u32.u64 %0, t; }" : "=r"(a) : "l"(p));
    return a;
}
__device__ __forceinline__ void cp16(uint32_t dst, const void* src) {
    asm volatile("cp.async.cg.shared.global [%0], [%1], 16;" :: "r"(dst), "l"(src));
}
#define CP_COMMIT() asm volatile("cp.async.commit_group;")
#define CP_WAIT1()  asm volatile("cp.async.wait_group 1;")

__device__ __forceinline__ void ldsm4(uint32_t* r, uint32_t addr) {
    asm volatile("ldmatrix.sync.aligned.m8n8.x4.shared.b16 {%0,%1,%2,%3}, [%4];"
                 : "=r"(r[0]), "=r"(r[1]), "=r"(r[2]), "=r"(r[3]) : "r"(addr));
}
__device__ __forceinline__ void mma_f16(float* d, const uint32_t* a, uint32_t b0, uint32_t b1) {
    asm volatile(
        "mma.sync.aligned.m16n8k16.row.col.f32.f16.f16.f32 "
        "{%0,%1,%2,%3}, {%4,%5,%6,%7}, {%8,%9}, {%0,%1,%2,%3};"
        : "+f"(d[0]), "+f"(d[1]), "+f"(d[2]), "+f"(d[3])
        : "r"(a[0]), "r"(a[1]), "r"(a[2]), "r"(a[3]), "r"(b0), "r"(b1));
}

// ---------------- weight conversion fp32 -> fp16 (also zeroes g_cnt) ----------------
__global__ __launch_bounds__(256) void convert_w(
    const float* __restrict__ w1, const float* __restrict__ w2, const float* __restrict__ w3,
    const float* __restrict__ ws1, const float* __restrict__ ws2, const float* __restrict__ ws3)
{
    if (blockIdx.x == 0 && blockIdx.y == 0 && threadIdx.x < NEXP)
        g_cnt[threadIdx.x] = 0;
    const int seg = blockIdx.y;
    const size_t n = (seg < 3) ? WBIG : WSML;
    const size_t i = ((size_t)blockIdx.x * 256 + threadIdx.x) * 8;
    if (i >= n) return;
    const float* src; __half* dst;
    switch (seg) {
        case 0: src = w1;  dst = g_w1h;        break;
        case 1: src = w3;  dst = g_w3h;        break;
        case 2: src = w2;  dst = g_w2h;        break;
        case 3: src = ws1; dst = g_w1h + WBIG; break;
        case 4: src = ws3; dst = g_w3h + WBIG; break;
        default: src = ws2; dst = g_w2h + WBIG; break;
    }
    float4 a = *(const float4*)(src + i);
    float4 b = *(const float4*)(src + i + 4);
    __half2 h0 = __floats2half2_rn(a.x, a.y), h1 = __floats2half2_rn(a.z, a.w);
    __half2 h2 = __floats2half2_rn(b.x, b.y), h3 = __floats2half2_rn(b.z, b.w);
    uint4 o;
    o.x = *(uint32_t*)&h0; o.y = *(uint32_t*)&h1;
    o.z = *(uint32_t*)&h2; o.w = *(uint32_t*)&h3;
    *(uint4*)(dst + i) = o;
}

// ---------------- gate ----------------
__global__ __launch_bounds__(256) void gate_kernel(const float* __restrict__ x,
                                                   const float* __restrict__ gw,
                                                   const float* __restrict__ gbias) {
    int t    = blockIdx.x * 8 + (threadIdx.x >> 5);
    int lane = threadIdx.x & 31;

    float4 xr[8];
    const float4* xp = (const float4*)(x + (size_t)t * DIM) + lane;
#pragma unroll
    for (int i = 0; i < 8; i++) xr[i] = xp[i * 32];

    __half* xo = g_xrh + (size_t)t * DIM + lane * 4;
#pragma unroll
    for (int i = 0; i < 8; i++) {
        __half2 lo = __floats2half2_rn(xr[i].x, xr[i].y);
        __half2 hi = __floats2half2_rn(xr[i].z, xr[i].w);
        uint2 u;
        u.x = *(uint32_t*)&lo; u.y = *(uint32_t*)&hi;
        *(uint2*)(xo + i * 128) = u;
    }

    float sc[NEXP];
#pragma unroll
    for (int e = 0; e < NEXP; e++) {
        const float4* w = (const float4*)(gw + (size_t)e * DIM) + lane;
        float acc = 0.f;
#pragma unroll
        for (int i = 0; i < 8; i++) {
            float4 wv = w[i * 32];
            acc += xr[i].x * wv.x + xr[i].y * wv.y + xr[i].z * wv.z + xr[i].w * wv.w;
        }
#pragma unroll
        for (int o = 16; o > 0; o >>= 1) acc += __shfl_xor_sync(0xffffffffu, acc, o);
        sc[e] = 1.f / (1.f + __expf(-acc));
    }
    if (lane == 0) {
        float s[NEXP];
#pragma unroll
        for (int e = 0; e < NEXP; e++) s[e] = sc[e] + gbias[e];
        float gm[NGRP];
#pragma unroll
        for (int g = 0; g < NGRP; g++) {
            float m = s[g * GSZ];
#pragma unroll
            for (int j = 1; j < GSZ; j++) m = fmaxf(m, s[g * GSZ + j]);
            gm[g] = m;
        }
        int g1 = 0;
#pragma unroll
        for (int g = 1; g < NGRP; g++) if (gm[g] > gm[g1]) g1 = g;
        int g2 = -1;
#pragma unroll
        for (int g = 0; g < NGRP; g++) {
            if (g == g1) continue;
            if (g2 < 0 || gm[g] > gm[g2]) g2 = g;
        }
        float sm[NEXP];
#pragma unroll
        for (int e = 0; e < NEXP; e++) {
            int g = e / GSZ;
            sm[e] = (g == g1 || g == g2) ? s[e] : -1e30f;
        }
#pragma unroll
        for (int k = 0; k < TOPK; k++) {
            int best = 0; float bv = -1e38f;
#pragma unroll
            for (int e = 0; e < NEXP; e++) if (sm[e] > bv) { bv = sm[e]; best = e; }
            sm[best] = -1e38f;
            int pos = atomicAdd(&g_cnt[best], 1);
            g_tok[best][pos]  = t;
            g_slot[best][pos] = (unsigned char)k;
            g_wt[best][pos]   = sc[best];
        }
    }
}

#define FILL_ROW(stageu, R, srcp) do {                                        \
        uint32_t _rb = (stageu) + (uint32_t)(R) * 128;                        \
        int _e7 = (R) & 7;                                                    \
        cp16(_rb + (uint32_t)(((h4 + 0) ^ _e7) << 4), (srcp) + 0);            \
        cp16(_rb + (uint32_t)(((h4 + 1) ^ _e7) << 4), (srcp) + 8);            \
        cp16(_rb + (uint32_t)(((h4 + 2) ^ _e7) << 4), (srcp) + 16);           \
        cp16(_rb + (uint32_t)(((h4 + 3) ^ _e7) << 4), (srcp) + 24);           \
    } while (0)

// =====================================================================
// stage A: act = silu(X@W1^T)*(X@W3^T) — 128 thr, 64x64 warp tiles,
// fragment double-buffered across ks
// =====================================================================
__global__ __launch_bounds__(128, 2) void ffn_in_mma()
{
    const int e   = blockIdx.z;
    const int cnt = (e == NEXP) ? T_TOK : g_cnt[e];
    const int m0  = blockIdx.x * 128;
    if (m0 >= cnt) return;
    const int n0  = blockIdx.y * 64;

    extern __shared__ char smc[];
    const uint32_t sb = smem_u32(smc);
    const int tid = threadIdx.x;

    const int fr = tid >> 1, h4 = (tid & 1) * 4;
    const int hoff = (tid & 1) * 32;
    int ai0 = m0 + fr;       if (ai0 > cnt - 1) ai0 = cnt - 1;
    int ai1 = m0 + fr + 64;  if (ai1 > cnt - 1) ai1 = cnt - 1;
    const int tok0 = (e == NEXP) ? (m0 + fr)      : g_tok[e][ai0];
    const int tok1 = (e == NEXP) ? (m0 + fr + 64) : g_tok[e][ai1];
    const __half* s0 = g_xrh + (size_t)tok0 * DIM + hoff;
    const __half* s1 = g_xrh + (size_t)tok1 * DIM + hoff;
    const __half* s2 = g_w1h + (size_t)e * INTER * DIM + (size_t)(n0 + fr) * DIM + hoff;
    const __half* s3 = g_w3h + (size_t)e * INTER * DIM + (size_t)(n0 + fr) * DIM + hoff;

    const int lane = tid & 31, warp = tid >> 5;
    const int wm = warp >> 1, wn = warp & 1;
    const int gid = lane >> 2, tig = lane & 3;

    const uint32_t aRowB = (uint32_t)(lane & 15) * 128;
    const uint32_t ahi   = (uint32_t)(lane >> 4) * 16;
    const uint32_t bRowB = ((uint32_t)(lane & 7) + (uint32_t)((lane >> 4) & 1) * 8) * 128;
    const uint32_t bhi   = (uint32_t)((lane >> 3) & 1) * 16;
    const uint32_t sw    = (uint32_t)(lane & 7) * 16;

    float acc1[4][4][4], acc3[4][4][4];
#pragma unroll
    for (int i = 0; i < 4; i++)
#pragma unroll
        for (int j = 0; j < 4; j++)
#pragma unroll
            for (int k = 0; k < 4; k++) { acc1[i][j][k] = 0.f; acc3[i][j][k] = 0.f; }

#define ISSUE_A(kk) do {                                        \
        uint32_t _st = sb + (uint32_t)(((kk) % 3) * STG_BYTES); \
        const int _ko = (kk) * 64;                              \
        FILL_ROW(_st, fr,        s0 + _ko);                     \
        FILL_ROW(_st, fr + 64,   s1 + _ko);                     \
        FILL_ROW(_st, fr + 128,  s2 + _ko);                     \
        FILL_ROW(_st, fr + 192,  s3 + _ko);                     \
        CP_COMMIT();                                            \
    } while (0)

// load all fragments for one ks into buffer b
#define LOADF_A(b, ks) do {                                                      \
        const uint32_t _akx = ((uint32_t)((ks) * 32) + ahi) ^ sw;                \
        const uint32_t _bkx = ((uint32_t)((ks) * 32) + bhi) ^ sw;                \
        ldsm4(af[b][0], Ab + 0u * 2048 + _akx);                                  \
        ldsm4(af[b][1], Ab + 1u * 2048 + _akx);                                  \
        ldsm4(af[b][2], Ab + 2u * 2048 + _akx);                                  \
        ldsm4(af[b][3], Ab + 3u * 2048 + _akx);                                  \
        ldsm4(b1f[b][0], B1b + 0u * 2048 + _bkx);                                \
        ldsm4(b1f[b][1], B1b + 1u * 2048 + _bkx);                                \
        ldsm4(b3f[b][0], B3b + 0u * 2048 + _bkx);                                \
        ldsm4(b3f[b][1], B3b + 1u * 2048 + _bkx);                                \
    } while (0)

#define MMA_A(b) do {                                                            \
        _Pragma("unroll")                                                        \
        for (int ntp = 0; ntp < 2; ntp++)                                        \
            _Pragma("unroll")                                                    \
            for (int mt = 0; mt < 4; mt++) {                                     \
                mma_f16(acc1[mt][2 * ntp + 0], af[b][mt], b1f[b][ntp][0], b1f[b][ntp][1]); \
                mma_f16(acc1[mt][2 * ntp + 1], af[b][mt], b1f[b][ntp][2], b1f[b][ntp][3]); \
                mma_f16(acc3[mt][2 * ntp + 0], af[b][mt], b3f[b][ntp][0], b3f[b][ntp][1]); \
                mma_f16(acc3[mt][2 * ntp + 1], af[b][mt], b3f[b][ntp][2], b3f[b][ntp][3]); \
            }                                                                    \
    } while (0)

    ISSUE_A(0);
    ISSUE_A(1);

    uint32_t af[2][4][4], b1f[2][2][4], b3f[2][2][4];

    const int KITER = DIM / 64;
    for (int kk = 0; kk < KITER; kk++) {
        CP_WAIT1();
        __syncthreads();
        if (kk + 2 < KITER) { ISSUE_A(kk + 2); } else { CP_COMMIT(); }

        const uint32_t stage = sb + (uint32_t)((kk % 3) * STG_BYTES);
        const uint32_t Ab  = stage + (uint32_t)(wm * 64) * 128 + aRowB;
        const uint32_t B1b = stage + 16384u + (uint32_t)(wn * 32) * 128 + bRowB;
        const uint32_t B3b = stage + 24576u + (uint32_t)(wn * 32) * 128 + bRowB;

        LOADF_A(0, 0);
#pragma unroll
        for (int ks = 0; ks < 4; ks++) {
            if (ks < 3) LOADF_A((ks + 1) & 1, ks + 1);
            MMA_A(ks & 1);
        }
    }

#pragma unroll
    for (int mt = 0; mt < 4; mt++) {
#pragma unroll
        for (int h = 0; h < 2; h++) {
            const int m = m0 + wm * 64 + mt * 16 + gid + h * 8;
            if (m >= cnt) continue;
            __half* dst = &g_acth[((size_t)e * T_TOK + m) * INTER + n0 + wn * 32];
#pragma unroll
            for (int nt = 0; nt < 4; nt++) {
                float v0 = acc1[mt][nt][h * 2 + 0], u0 = acc3[mt][nt][h * 2 + 0];
                float v1 = acc1[mt][nt][h * 2 + 1], u1 = acc3[mt][nt][h * 2 + 1];
                *(__half2*)(dst + nt * 8 + tig * 2) =
                    __floats2half2_rn((v0 / (1.f + __expf(-v0))) * u0,
                                      (v1 / (1.f + __expf(-v1))) * u1);
            }
        }
    }
#undef ISSUE_A
#undef LOADF_A
#undef MMA_A
}

// =====================================================================
// stage B: y = act @ W2^T — 128 thr, 64x64 warp tiles, frag double-buffered
// =====================================================================
__global__ __launch_bounds__(128, 2) void ffn_out_mma(float* __restrict__ out)
{
    const int e   = blockIdx.z;
    const int cnt = (e == NEXP) ? T_TOK : g_cnt[e];
    const int m0  = blockIdx.x * 128;
    if (m0 >= cnt) return;
    const int n0  = blockIdx.y * 128;

    extern __shared__ char smc[];
    const uint32_t sb = smem_u32(smc);
    const int tid = threadIdx.x;

    const int fr = tid >> 1, h4 = (tid & 1) * 4;
    const int hoff = (tid & 1) * 32;
    int ai0 = m0 + fr;      if (ai0 > cnt - 1) ai0 = cnt - 1;
    int ai1 = m0 + fr + 64; if (ai1 > cnt - 1) ai1 = cnt - 1;
    const __half* s0 = g_acth + ((size_t)e * T_TOK + ai0) * INTER + hoff;
    const __half* s1 = g_acth + ((size_t)e * T_TOK + ai1) * INTER + hoff;
    const __half* s2 = g_w2h + (size_t)e * DIM * INTER + (size_t)(n0 + fr) * INTER + hoff;
    const __half* s3 = s2 + (size_t)64 * INTER;

    const int lane = tid & 31, warp = tid >> 5;
    const int wm = warp >> 1, wn = warp & 1;
    const int gid = lane >> 2, tig = lane & 3;

    const uint32_t aRowB = (uint32_t)(lane & 15) * 128;
    const uint32_t ahi   = (uint32_t)(lane >> 4) * 16;
    const uint32_t bRowB = ((uint32_t)(lane & 7) + (uint32_t)((lane >> 4) & 1) * 8) * 128;
    const uint32_t bhi   = (uint32_t)((lane >> 3) & 1) * 16;
    const uint32_t sw    = (uint32_t)(lane & 7) * 16;

    float acc[4][8][4];
#pragma unroll
    for (int i = 0; i < 4; i++)
#pragma unroll
        for (int j = 0; j < 8; j++)
#pragma unroll
            for (int k = 0; k < 4; k++) acc[i][j][k] = 0.f;

#define ISSUE_B(kk) do {                                        \
        uint32_t _st = sb + (uint32_t)(((kk) % 3) * STG_BYTES); \
        const int _ko = (kk) * 64;                              \
        FILL_ROW(_st, fr,        s0 + _ko);                     \
        FILL_ROW(_st, fr + 64,   s1 + _ko);                     \
        FILL_ROW(_st, fr + 128,  s2 + _ko);                     \
        FILL_ROW(_st, fr + 192,  s3 + _ko);                     \
        CP_COMMIT();                                            \
    } while (0)

#define LOADF_B(b, ks) do {                                                      \
        const uint32_t _akx = ((uint32_t)((ks) * 32) + ahi) ^ sw;                \
        const uint32_t _bkx = ((uint32_t)((ks) * 32) + bhi) ^ sw;                \
        ldsm4(af[b][0], Ab + 0u * 2048 + _akx);                                  \
        ldsm4(af[b][1], Ab + 1u * 2048 + _akx);                                  \
        ldsm4(af[b][2], Ab + 2u * 2048 + _akx);                                  \
        ldsm4(af[b][3], Ab + 3u * 2048 + _akx);                                  \
        ldsm4(bf[b][0], Bb + 0u * 2048 + _bkx);                                  \
        ldsm4(bf[b][1], Bb + 1u * 2048 + _bkx);                                  \
        ldsm4(bf[b][2], Bb + 2u * 2048 + _bkx);                                  \
        ldsm4(bf[b][3], Bb + 3u * 2048 + _bkx);                                  \
    } while (0)

#define MMA_B(b) do {                                                            \
        _Pragma("unroll")                                                        \
        for (int ntp = 0; ntp < 4; ntp++)                                        \
            _Pragma("unroll")                                                    \
            for (int mt = 0; mt < 4; mt++) {                                     \
                mma_f16(acc[mt][2 * ntp + 0], af[b][mt], bf[b][ntp][0], bf[b][ntp][1]); \
                mma_f16(acc[mt][2 * ntp + 1], af[b][mt], bf[b][ntp][2], bf[b][ntp][3]); \
            }                                                                    \
    } while (0)

    ISSUE_B(0);
    ISSUE_B(1);

    uint32_t af[2][4][4], bf[2][4][4];

    const int KITER = INTER / 64;
    for (int kk = 0; kk < KITER; kk++) {
        CP_WAIT1();
        __syncthreads();
        if (kk + 2 < KITER) { ISSUE_B(kk + 2); } else { CP_COMMIT(); }

        const uint32_t stage = sb + (uint32_t)((kk % 3) * STG_BYTES);
        const uint32_t Ab = stage + (uint32_t)(wm * 64) * 128 + aRowB;
        const uint32_t Bb = stage + 16384u + (uint32_t)(wn * 64) * 128 + bRowB;

        LOADF_B(0, 0);
#pragma unroll
        for (int ks = 0; ks < 4; ks++) {
            if (ks < 3) LOADF_B((ks + 1) & 1, ks + 1);
            MMA_B(ks & 1);
        }
    }

#pragma unroll
    for (int mt = 0; mt < 4; mt++) {
#pragma unroll
        for (int h = 0; h < 2; h++) {
            const int m = m0 + wm * 64 + mt * 16 + gid + h * 8;
            if (m >= cnt) continue;
            float wt = 1.f;
            float* dst;
            if (e == NEXP) {
                dst = out + (size_t)m * DIM + n0 + wn * 64;
            } else {
                const int tokm = g_tok[e][m];
                const int sl   = g_slot[e][m];
                wt             = g_wt[e][m];
                dst = &g_ybuf[sl][(size_t)tokm * DIM + n0 + wn * 64];
            }
#pragma unroll
            for (int nt = 0; nt < 8; nt++) {
                *(float2*)(dst + nt * 8 + tig * 2) =
                    make_float2(acc[mt][nt][h * 2 + 0] * wt,
                                acc[mt][nt][h * 2 + 1] * wt);
            }
        }
    }
#undef ISSUE_B
#undef LOADF_B
#undef MMA_B
}

// ---------------- reduce ----------------
__global__ void reduce_kernel(float* __restrict__ out) {
    size_t idx = ((size_t)blockIdx.x * blockDim.x + threadIdx.x) * 4;
    if (idx < (size_t)T_TOK * DIM) {
        float4 o = *(float4*)(out + idx);
        float4 a = *(const float4*)(&g_ybuf[0][idx]);
        float4 b = *(const float4*)(&g_ybuf[1][idx]);
        float4 c = *(const float4*)(&g_ybuf[2][idx]);
        float4 d = *(const float4*)(&g_ybuf[3][idx]);
        o.x += a.x + b.x + c.x + d.x;
        o.y += a.y + b.y + c.y + d.y;
        o.z += a.z + b.z + c.z + d.z;
        o.w += a.w + b.w + c.w + d.w;
        *(float4*)(out + idx) = o;
    }
}

// ---------------- launch ----------------
extern "C" void kernel_launch(void* const* d_in, const int* in_sizes, int n_in,
                              void* d_out, int out_size) {
    const float* x   = (const float*)d_in[0];
    const float* gw  = (const float*)d_in[1];
    const float* gb  = (const float*)d_in[2];
    const float* w1  = (const float*)d_in[3];
    const float* w2  = (const float*)d_in[4];
    const float* w3  = (const float*)d_in[5];
    const float* ws1 = (const float*)d_in[6];
    const float* ws2 = (const float*)d_in[7];
    const float* ws3 = (const float*)d_in[8];
    float* out = (float*)d_out;

    cudaFuncSetAttribute(ffn_in_mma,  cudaFuncAttributeMaxDynamicSharedMemorySize, SMEM_BYTES);
    cudaFuncSetAttribute(ffn_out_mma, cudaFuncAttributeMaxDynamicSharedMemorySize, SMEM_BYTES);

    convert_w<<<dim3(4096, 6), 256>>>(w1, w2, w3, ws1, ws2, ws3);
    gate_kernel<<<T_TOK / 8, 256>>>(x, gw, gb);
    ffn_in_mma<<<dim3(T_TOK / 128, INTER / 64, NE1), 128, SMEM_BYTES>>>();
    ffn_out_mma<<<dim3(T_TOK / 128, DIM / 128, NE1), 128, SMEM_BYTES>>>(out);
    reduce_kernel<<<(T_TOK * DIM / 4 + 255) / 256, 256>>>(out);
}